// round 13
// baseline (speedup 1.0000x reference)
#include <cuda_runtime.h>
#include <cuda_bf16.h>
#include <cstdint>

#define NATOMS 131072
#define MNBR   12
#define ORIG   92
#define NBRF   41
#define AF     64
#define HDIM   128
#define NPROP  2
#define NCONV  3
#define NSEG   1024
#define FIN    169
#define C2     128
#define EPSBN  1e-5f

#define NPAIR  (NATOMS*MNBR)           // 1572864
#define TILE   48                      // 4 atoms x 12 nbrs
#define NTILE  (NPAIR/TILE)            // 32768
#define NB     592                     // 148 SMs x 4 resident blocks (pass 1)
#define NB2    1184                    // streaming pass 2

// pass-1 dynamic smem (double buffered)
#define A_BYTES (TILE*NBRF*4)          // 7872
#define A_CHUNK (A_BYTES/16)           // 492
#define T_OFF   A_BYTES                // bf16 rows: 256B data padded to 272B
#define TROWB   272
#define T_BYTES (TILE*TROWB)           // 13056
#define S_OFF   (T_OFF + T_BYTES)      // fp32 rows padded: 528B (bias folded)
#define SROW    132
#define S_BYTES (4*SROW*4)             // 2112
#define BUFSZ   (S_OFF + S_BYTES)      // 23040
#define DSMEM   (2*BUFSZ)              // 46080

// channel base for warp w, n-tile nt: filter (nt 0,1) then core partner (+64)
#define CHBASE(w, nt) ((w)*16 + ((nt)&1)*8 + ((nt)>>1)*64)

// ---------------- scratch ----------------------------------------------------
__device__ float g_x[(size_t)NATOMS*AF];
__device__ float g_S[(size_t)NATOMS*C2];           // fp32, bias folded in
__device__ __nv_bfloat16 g_T[(size_t)NATOMS*C2];   // 33.5 MB, bf16 (L2-resident)
__device__ __nv_bfloat16 g_gated[(size_t)NPAIR*C2];// 402 MB, bf16
__device__ float g_nbrsum[(size_t)NATOMS*AF];
__device__ float g_part1[2048*C2];
__device__ float g_part2[2048*C2];
__device__ float g_partA[2048*AF];
__device__ float g_partB[2048*AF];
__device__ float g_scale1[C2], g_shift1[C2];
__device__ float g_scale2[AF], g_shift2[AF];
__device__ unsigned g_c1 = 0, g_c2 = 0;

// ---------------- helpers ----------------------------------------------------
__device__ __forceinline__ float sp(float x) {
    return fmaxf(x, 0.f) + __logf(1.f + __expf(-fabsf(x)));
}
__device__ __forceinline__ float sig(float x) {
    return 1.f / (1.f + __expf(-x));
}
__device__ __forceinline__ int lbound(const int* __restrict__ a, int n, int v) {
    int lo = 0, hi = n;
    while (lo < hi) { int mid = (lo + hi) >> 1; if (a[mid] < v) lo = mid + 1; else hi = mid; }
    return lo;
}
__device__ __forceinline__ unsigned f2tf32(float v) {
    unsigned u; asm("cvt.rna.tf32.f32 %0, %1;" : "=r"(u) : "f"(v)); return u;
}
__device__ __forceinline__ void cp16(uint32_t dst, const void* src) {
    asm volatile("cp.async.cg.shared.global [%0], [%1], 16;\n" :: "r"(dst), "l"(src));
}
__device__ __forceinline__ void cp_commit() {
    asm volatile("cp.async.commit_group;\n");
}
__device__ __forceinline__ float bfly3(float v) {
    v += __shfl_xor_sync(0xffffffffu, v, 4);
    v += __shfl_xor_sync(0xffffffffu, v, 8);
    v += __shfl_xor_sync(0xffffffffu, v, 16);
    return v;
}
__device__ __forceinline__ float2 ldbf2(const char* p) {
    __nv_bfloat162 h = *(const __nv_bfloat162*)p;
    return __bfloat1622float2(h);
}
__device__ __forceinline__ float2 ldbf2cs(const char* p) {
    unsigned u = __ldcs((const unsigned*)p);
    __nv_bfloat162 h = *(__nv_bfloat162*)&u;
    return __bfloat1622float2(h);
}

#define MMA_TF32(cr, a0, a1, a2, a3, b0, b1) \
    asm("mma.sync.aligned.m16n8k8.row.col.f32.tf32.tf32.f32 " \
        "{%0,%1,%2,%3}, {%4,%5,%6,%7}, {%8,%9}, {%0,%1,%2,%3};" \
        : "+f"(cr[0]), "+f"(cr[1]), "+f"(cr[2]), "+f"(cr[3]) \
        : "r"(a0), "r"(a1), "r"(a2), "r"(a3), "r"(b0), "r"(b1));

// ---------------- embed: x = atom_fea @ W_embed + b (tf32 MMA) ---------------
__global__ void __launch_bounds__(128) k_embed(const float* __restrict__ af,
        const float* __restrict__ W, const float* __restrict__ b) {
    int tid = threadIdx.x, warp = tid >> 5, lane = tid & 31;
    int gr = lane >> 2, gc = lane & 3;
    unsigned bfr[12][2][2];
    #pragma unroll
    for (int ks = 0; ks < 12; ks++)
        #pragma unroll
        for (int nt = 0; nt < 2; nt++) {
            int c = warp*16 + nt*8 + gr;
            int k0 = ks*8 + gc, k1 = k0 + 4;
            bfr[ks][nt][0] = f2tf32((k0 < ORIG) ? W[k0*AF + c] : 0.f);
            bfr[ks][nt][1] = f2tf32((k1 < ORIG) ? W[k1*AF + c] : 0.f);
        }
    __shared__ unsigned Ash[32*100];
    __shared__ float Csh[32*68];
    for (int tt = 0; tt < 2; tt++) {
        int t = blockIdx.x + tt*2048;
        int a0 = t*32;
        for (int i = tid; i < 32*100; i += 128) {
            int r = i/100, k = i - r*100;
            float v = (k < ORIG) ? af[(size_t)(a0+r)*ORIG + k] : 0.f;
            Ash[i] = f2tf32(v);
        }
        __syncthreads();
        #pragma unroll
        for (int mt = 0; mt < 2; mt++) {
            float cr[2][4] = {};
            #pragma unroll
            for (int ks = 0; ks < 12; ks++) {
                unsigned a0f = Ash[(mt*16+gr)*100   + ks*8+gc];
                unsigned a1f = Ash[(mt*16+gr+8)*100 + ks*8+gc];
                unsigned a2f = Ash[(mt*16+gr)*100   + ks*8+gc+4];
                unsigned a3f = Ash[(mt*16+gr+8)*100 + ks*8+gc+4];
                #pragma unroll
                for (int nt = 0; nt < 2; nt++)
                    MMA_TF32(cr[nt], a0f, a1f, a2f, a3f, bfr[ks][nt][0], bfr[ks][nt][1]);
            }
            #pragma unroll
            for (int nt = 0; nt < 2; nt++) {
                int cb = warp*16 + nt*8 + gc*2;
                Csh[(mt*16+gr)*68   + cb]   = cr[nt][0];
                Csh[(mt*16+gr)*68   + cb+1] = cr[nt][1];
                Csh[(mt*16+gr+8)*68 + cb]   = cr[nt][2];
                Csh[(mt*16+gr+8)*68 + cb+1] = cr[nt][3];
            }
        }
        __syncthreads();
        #pragma unroll
        for (int i = 0; i < 4; i++) {
            int lin = tid + i*128;
            int r = lin >> 4, c4 = lin & 15;
            float4 v = *(float4*)&Csh[r*68 + c4*4];
            float4 bi = *(const float4*)&b[c4*4];
            v.x += bi.x; v.y += bi.y; v.z += bi.z; v.w += bi.w;
            *(float4*)&g_x[(size_t)(a0+r)*AF + c4*4] = v;
        }
        __syncthreads();
    }
}

// ---------------- proj: [S|T] = x @ W[0:128,:]; bias folded into S (fp32) ----
__global__ void __launch_bounds__(256) k_proj(const float* __restrict__ convW,
        const float* __restrict__ convB, int l, int fuse) {
    const float* W = convW + (size_t)l*FIN*C2;
    int tid = threadIdx.x, warp = tid >> 5, lane = tid & 31;
    int gr = lane >> 2, gc = lane & 3;
    int isT = (warp >= 4), w4 = warp & 3;
    int rbase = isT ? AF : 0;
    unsigned bfr[8][4][2];
    #pragma unroll
    for (int ks = 0; ks < 8; ks++)
        #pragma unroll
        for (int nt = 0; nt < 4; nt++) {
            int c = w4*32 + nt*8 + gr;
            int k0 = ks*8 + gc, k1 = k0 + 4;
            bfr[ks][nt][0] = f2tf32(W[(rbase+k0)*C2 + c]);
            bfr[ks][nt][1] = f2tf32(W[(rbase+k1)*C2 + c]);
        }
    __shared__ unsigned Ash[32*68];
    __shared__ float Csh[32*264];
    for (int tt = 0; tt < 2; tt++) {
        int t = blockIdx.x + tt*2048;
        int a0 = t*32;
        {
            int r = tid >> 3, q = tid & 7;
            size_t base = (size_t)(a0+r)*AF + q*8;
            float4 v0 = *(const float4*)&g_x[base];
            float4 v1 = *(const float4*)&g_x[base+4];
            if (fuse) {
                float4 n0 = *(const float4*)&g_nbrsum[base];
                float4 n1 = *(const float4*)&g_nbrsum[base+4];
                float4 sc0 = *(const float4*)&g_scale2[q*8];
                float4 sc1 = *(const float4*)&g_scale2[q*8+4];
                float4 sh0 = *(const float4*)&g_shift2[q*8];
                float4 sh1 = *(const float4*)&g_shift2[q*8+4];
                v0.x = sp(v0.x + n0.x*sc0.x + sh0.x);
                v0.y = sp(v0.y + n0.y*sc0.y + sh0.y);
                v0.z = sp(v0.z + n0.z*sc0.z + sh0.z);
                v0.w = sp(v0.w + n0.w*sc0.w + sh0.w);
                v1.x = sp(v1.x + n1.x*sc1.x + sh1.x);
                v1.y = sp(v1.y + n1.y*sc1.y + sh1.y);
                v1.z = sp(v1.z + n1.z*sc1.z + sh1.z);
                v1.w = sp(v1.w + n1.w*sc1.w + sh1.w);
                *(float4*)&g_x[base]   = v0;
                *(float4*)&g_x[base+4] = v1;
            }
            unsigned* dst = &Ash[r*68 + q*8];
            dst[0]=f2tf32(v0.x); dst[1]=f2tf32(v0.y); dst[2]=f2tf32(v0.z); dst[3]=f2tf32(v0.w);
            dst[4]=f2tf32(v1.x); dst[5]=f2tf32(v1.y); dst[6]=f2tf32(v1.z); dst[7]=f2tf32(v1.w);
        }
        __syncthreads();
        #pragma unroll
        for (int mt = 0; mt < 2; mt++) {
            float cr[4][4] = {};
            #pragma unroll
            for (int ks = 0; ks < 8; ks++) {
                unsigned a0f = Ash[(mt*16+gr)*68   + ks*8+gc];
                unsigned a1f = Ash[(mt*16+gr+8)*68 + ks*8+gc];
                unsigned a2f = Ash[(mt*16+gr)*68   + ks*8+gc+4];
                unsigned a3f = Ash[(mt*16+gr+8)*68 + ks*8+gc+4];
                #pragma unroll
                for (int nt = 0; nt < 4; nt++)
                    MMA_TF32(cr[nt], a0f, a1f, a2f, a3f, bfr[ks][nt][0], bfr[ks][nt][1]);
            }
            #pragma unroll
            for (int nt = 0; nt < 4; nt++) {
                int cb = (isT ? 132 : 0) + w4*32 + nt*8 + gc*2;
                Csh[(mt*16+gr)*264   + cb]   = cr[nt][0];
                Csh[(mt*16+gr)*264   + cb+1] = cr[nt][1];
                Csh[(mt*16+gr+8)*264 + cb]   = cr[nt][2];
                Csh[(mt*16+gr+8)*264 + cb+1] = cr[nt][3];
            }
        }
        __syncthreads();
        // S: fp32, bias folded in
        #pragma unroll
        for (int i = 0; i < 4; i++) {
            int lin = tid + i*256;
            int r = lin >> 5, c4 = lin & 31;
            float4 v  = *(float4*)&Csh[r*264 + c4*4];
            float4 bi = *(const float4*)&convB[l*C2 + c4*4];
            v.x += bi.x; v.y += bi.y; v.z += bi.z; v.w += bi.w;
            *(float4*)&g_S[(size_t)(a0+r)*C2 + c4*4] = v;
        }
        // T: bf16 (32 rows x 256B)
        #pragma unroll
        for (int i = 0; i < 2; i++) {
            int lin = tid + i*256;
            int r = lin >> 4, c8 = lin & 15;
            const float* src = &Csh[r*264 + 132 + c8*8];
            float4 v0 = *(const float4*)src, v1 = *(const float4*)(src+4);
            __nv_bfloat162 h0 = __float22bfloat162_rn(make_float2(v0.x, v0.y));
            __nv_bfloat162 h1 = __float22bfloat162_rn(make_float2(v0.z, v0.w));
            __nv_bfloat162 h2 = __float22bfloat162_rn(make_float2(v1.x, v1.y));
            __nv_bfloat162 h3 = __float22bfloat162_rn(make_float2(v1.z, v1.w));
            uint4 pk;
            pk.x = *(unsigned*)&h0; pk.y = *(unsigned*)&h1;
            pk.z = *(unsigned*)&h2; pk.w = *(unsigned*)&h3;
            *(uint4*)((char*)g_T + (size_t)(a0+r)*256 + c8*16) = pk;
        }
        __syncthreads();
    }
}

// ======= pass-1 machinery (4 warps, 32 ch/warp) ==============================
__device__ __forceinline__ void prefetch_tile(int t, uint32_t bb,
        const float* __restrict__ nbr_fea, const int* __restrict__ idx, int tid) {
    const char* asrc = (const char*)nbr_fea + (size_t)t * A_BYTES;
    #pragma unroll
    for (int i = 0; i < 4; i++) {
        int c = tid + i*128;
        if (c < A_CHUNK) cp16(bb + c*16, asrc + c*16);
    }
    int p0 = t * TILE;
    #pragma unroll
    for (int i = 0; i < 6; i++) {               // bf16 T rows: 256B each
        int lin = tid + i*128;
        int r = lin >> 4, cx = lin & 15;
        int j = __ldg(&idx[p0 + r]);
        cp16(bb + T_OFF + r*TROWB + cx*16, (const char*)g_T + ((size_t)j << 8) + cx*16);
    }
    { int r = tid >> 5, cx = tid & 31;           // fp32 S rows: 512B each
      cp16(bb + S_OFF + r*528 + cx*16,
           (const char*)g_S + ((size_t)(t*4 + r) << 9) + cx*16); }
    cp_commit();
}

// MMA over k=0..39 (tf32), then k=40 via fp32 FFMA.
#define DO_MMA(mt, cr, Au, Af) \
        _Pragma("unroll") for (int ks = 0; ks < 5; ks++) {                      \
            unsigned a0 = Au[((mt)*16+gr)*NBRF   + ks*8+gc];                    \
            unsigned a1 = Au[((mt)*16+gr+8)*NBRF + ks*8+gc];                    \
            unsigned a2 = Au[((mt)*16+gr)*NBRF   + ks*8+gc+4];                  \
            unsigned a3 = Au[((mt)*16+gr+8)*NBRF + ks*8+gc+4];                  \
            _Pragma("unroll") for (int nt = 0; nt < 4; nt++)                    \
                MMA_TF32(cr[nt], a0, a1, a2, a3, bfr[ks][nt][0], bfr[ks][nt][1]); \
        }                                                                       \
        {   float a40_0 = Af[((mt)*16+gr)*NBRF + 40];                           \
            float a40_1 = Af[((mt)*16+gr+8)*NBRF + 40];                         \
            _Pragma("unroll") for (int nt = 0; nt < 4; nt++) {                  \
                cr[nt][0] += a40_0*w40[nt][0];  cr[nt][1] += a40_0*w40[nt][1];  \
                cr[nt][2] += a40_1*w40[nt][0];  cr[nt][3] += a40_1*w40[nt][1];  \
            }                                                                   \
        }

// ---------------- pass 1: gated -> bf16 store + BN1 stats + fused reduce -----
__global__ void __launch_bounds__(128, 4) k_stats(const float* __restrict__ nbr_fea,
        const int* __restrict__ idx, const float* __restrict__ convW,
        const float* __restrict__ g1, const float* __restrict__ be1, int l) {
    const float* W3 = convW + (size_t)l*FIN*C2 + (size_t)C2*C2;
    int tid  = threadIdx.x;
    int warp = tid >> 5, lane = tid & 31;
    int gr = lane >> 2, gc = lane & 3;
    unsigned bfr[5][4][2];
    #pragma unroll
    for (int ks = 0; ks < 5; ks++)
        #pragma unroll
        for (int nt = 0; nt < 4; nt++) {
            int c  = CHBASE(warp, nt) + gr;
            int k0 = ks*8 + gc, k1 = k0 + 4;
            bfr[ks][nt][0] = f2tf32(W3[k0*C2 + c]);
            bfr[ks][nt][1] = f2tf32(W3[k1*C2 + c]);
        }
    float w40[4][2];
    #pragma unroll
    for (int nt = 0; nt < 4; nt++) {
        w40[nt][0] = W3[40*C2 + CHBASE(warp, nt) + gc*2];
        w40[nt][1] = W3[40*C2 + CHBASE(warp, nt) + gc*2 + 1];
    }
    extern __shared__ char smx[];
    uint32_t sbase = (uint32_t)__cvta_generic_to_shared(smx);

    float sch[4][2] = {}, sch2[4][2] = {};
    int t = blockIdx.x;
    prefetch_tile(t, sbase, nbr_fea, idx, tid);
    int cur = 0;
    for (; t < NTILE; t += NB) {
        int tn = t + NB;
        if (tn < NTILE) {
            prefetch_tile(tn, sbase + (1-cur)*BUFSZ, nbr_fea, idx, tid);
            asm volatile("cp.async.wait_group 1;\n");
        } else {
            asm volatile("cp.async.wait_group 0;\n");
        }
        __syncthreads();
        const unsigned* Au = (const unsigned*)(smx + cur*BUFSZ);
        const float*    Af = (const float*)(smx + cur*BUFSZ);
        char*           TB = smx + cur*BUFSZ + T_OFF;
        const float*    Ssh = (const float*)(smx + cur*BUFSZ + S_OFF);
        #pragma unroll
        for (int mt = 0; mt < 3; mt++) {
            float cr[4][4] = {};
            DO_MMA(mt, cr, Au, Af)
            int r0 = mt*16 + gr, r1 = r0 + 8;
            int a0i = r0 / MNBR, a1i = r1 / MNBR;
            #pragma unroll
            for (int nt = 0; nt < 4; nt++) {
                int c0 = CHBASE(warp, nt) + gc*2;
                float2 t0 = ldbf2(TB + r0*TROWB + c0*2);
                float2 s0 = *(const float2*)&Ssh[a0i*SROW + c0];
                float2 t1 = ldbf2(TB + r1*TROWB + c0*2);
                float2 s1 = *(const float2*)&Ssh[a1i*SROW + c0];
                float v0 = cr[nt][0] + t0.x + s0.x;
                float v1 = cr[nt][1] + t0.y + s0.y;
                float v2 = cr[nt][2] + t1.x + s1.x;
                float v3 = cr[nt][3] + t1.y + s1.y;
                sch[nt][0] += v0 + v2; sch2[nt][0] += v0*v0 + v2*v2;
                sch[nt][1] += v1 + v3; sch2[nt][1] += v1*v1 + v3*v3;
                // write gated (bf16) in place over dead T slots (exclusive per thread)
                *(__nv_bfloat162*)(TB + r0*TROWB + c0*2) =
                    __float22bfloat162_rn(make_float2(v0, v1));
                *(__nv_bfloat162*)(TB + r1*TROWB + c0*2) =
                    __float22bfloat162_rn(make_float2(v2, v3));
            }
        }
        __syncthreads();
        // coalesced copy gated tile to global (48 rows x 256B)
        {
            size_t p0 = (size_t)t * TILE;
            #pragma unroll
            for (int i = 0; i < 6; i++) {
                int lin = tid + i*128;
                int r = lin >> 4, cx = lin & 15;
                uint4 val = *(const uint4*)(TB + r*TROWB + cx*16);
                __stcs((uint4*)((char*)g_gated + (p0 + r)*256 + cx*16), val);
            }
        }
        __syncthreads();
        cur ^= 1;
    }
    #pragma unroll
    for (int nt = 0; nt < 4; nt++)
        #pragma unroll
        for (int j = 0; j < 2; j++) {
            sch[nt][j]  = bfly3(sch[nt][j]);
            sch2[nt][j] = bfly3(sch2[nt][j]);
        }
    if (lane < 4) {
        #pragma unroll
        for (int nt = 0; nt < 4; nt++)
            #pragma unroll
            for (int j = 0; j < 2; j++) {
                int c = CHBASE(warp, nt) + lane*2 + j;
                g_part1[blockIdx.x*C2 + c] = sch[nt][j];
                g_part2[blockIdx.x*C2 + c] = sch2[nt][j];
            }
    }
    __shared__ int amLast;
    __threadfence();
    __syncthreads();
    if (tid == 0) amLast = (atomicAdd(&g_c1, 1u) == NB - 1);
    __syncthreads();
    if (amLast) {
        int c = tid;
        float s = 0.f, s2 = 0.f;
        for (int i = 0; i < NB; i++) {
            s += g_part1[i*C2 + c]; s2 += g_part2[i*C2 + c];
        }
        float cnt  = (float)((size_t)NATOMS * MNBR);
        float mean = s / cnt;
        float var  = s2 / cnt - mean*mean;
        float rstd = rsqrtf(var + EPSBN);
        float sc   = g1[l*C2 + c] * rstd;
        g_scale1[c] = sc;
        g_shift1[c] = be1[l*C2 + c] - mean*sc;
        if (tid == 0) g_c1 = 0;
    }
}

// ---------------- pass 2: stream gated, BN1 + act + nbr-sum + fused BN2 ------
// block 256 = 8 atom-groups x 32 threads; thread j handles ch {2j,2j+1} + {+64}
__global__ void __launch_bounds__(256) k_act(const float* __restrict__ g2,
        const float* __restrict__ be2, int l) {
    int tid = threadIdx.x, j = tid & 31, ty = tid >> 5;
    float2 scf = *(const float2*)&g_scale1[2*j];
    float2 shf = *(const float2*)&g_shift1[2*j];
    float2 scc = *(const float2*)&g_scale1[64 + 2*j];
    float2 shc = *(const float2*)&g_shift1[64 + 2*j];
    float sA0 = 0.f, sA1 = 0.f, s2A0 = 0.f, s2A1 = 0.f;
    for (int n = blockIdx.x*8 + ty; n < NATOMS; n += NB2*8) {
        const char* gp = (const char*)g_gated + (size_t)n * MNBR * 256;
        float a0 = 0.f, a1 = 0.f;
        #pragma unroll
        for (int m = 0; m < MNBR; m++) {
            float2 f = ldbf2cs(gp + m*256 + j*4);
            float2 c = ldbf2cs(gp + m*256 + 128 + j*4);
            a0 += sig(f.x*scf.x + shf.x) * sp(c.x*scc.x + shc.x);
            a1 += sig(f.y*scf.y + shf.y) * sp(c.y*scc.y + shc.y);
        }
        *(float2*)&g_nbrsum[(size_t)n*AF + 2*j] = make_float2(a0, a1);
        sA0 += a0; s2A0 += a0*a0;
        sA1 += a1; s2A1 += a1*a1;
    }
    __shared__ float redA[8][AF], redB[8][AF];
    redA[ty][2*j]   = sA0; redB[ty][2*j]   = s2A0;
    redA[ty][2*j+1] = sA1; redB[ty][2*j+1] = s2A1;
    __syncthreads();
    if (tid < AF) {
        float s = 0.f, s2 = 0.f;
        #pragma unroll
        for (int g = 0; g < 8; g++) { s += redA[g][tid]; s2 += redB[g][tid]; }
        g_partA[blockIdx.x*AF + tid] = s;
        g_partB[blockIdx.x*AF + tid] = s2;
    }
    __shared__ int amLast;
    __threadfence();
    __syncthreads();
    if (tid == 0) amLast = (atomicAdd(&g_c2, 1u) == NB2 - 1);
    __syncthreads();
    if (amLast && tid < AF) {
        int c = tid;
        float s = 0.f, s2 = 0.f;
        for (int i = 0; i < NB2; i++) {
            s += g_partA[i*AF + c]; s2 += g_partB[i*AF + c];
        }
        float cnt  = (float)NATOMS;
        float mean = s / cnt;
        float var  = s2 / cnt - mean*mean;
        float rstd = rsqrtf(var + EPSBN);
        float sc   = g2[l*AF + c] * rstd;
        g_scale2[c] = sc;
        g_shift2[c] = be2[l*AF + c] - mean*sc;
        if (tid == 0) g_c2 = 0;
    }
}

// ---------------- finish: final update + segment mean pool + MLP head --------
__global__ void __launch_bounds__(128) k_finish(const int* __restrict__ cidx,
        const float* __restrict__ W1, const float* __restrict__ b1,
        const float* __restrict__ W2, const float* __restrict__ b2,
        float* __restrict__ out, float* __restrict__ out_crys) {
    int b = blockIdx.x, tid = threadIdx.x;
    int lo = lbound(cidx, NATOMS, b);
    int hi = lbound(cidx, NATOMS, b + 1);
    int f = tid & 63, half = tid >> 6;
    float sc2 = g_scale2[f], sh2v = g_shift2[f];
    float s = 0.f;
    for (int a = lo + half; a < hi; a += 2) {
        size_t i = (size_t)a*AF + f;
        s += sp(g_x[i] + g_nbrsum[i]*sc2 + sh2v);
    }
    __shared__ float psum[2][AF];
    __shared__ float av[AF];
    __shared__ float red[HDIM];
    psum[half][f] = s;
    __syncthreads();
    if (tid < AF) {
        float v = (psum[0][tid] + psum[1][tid]) / fmaxf((float)(hi - lo), 1.f);
        out_crys[b*AF + tid] = v;
        av[tid] = sp(v);
    }
    __syncthreads();
    for (int p = 0; p < NPROP; p++) {
        float acc = b1[p*HDIM + tid];
        #pragma unroll
        for (int k = 0; k < AF; k++) acc += av[k] * W1[((size_t)p*AF + k)*HDIM + tid];
        red[tid] = sp(acc) * W2[p*HDIM + tid];
        __syncthreads();
        for (int o = 64; o > 0; o >>= 1) {
            if (tid < o) red[tid] += red[tid+o];
            __syncthreads();
        }
        if (tid == 0) out[b*NPROP + p] = red[0] + b2[p];
        __syncthreads();
    }
}

// ---------------- launch --------------------------------------------------------
extern "C" void kernel_launch(void* const* d_in, const int* in_sizes, int n_in,
                              void* d_out, int out_size) {
    const float* atom_fea = (const float*)d_in[0];
    const float* nbr_fea  = (const float*)d_in[1];
    const float* W_embed  = (const float*)d_in[2];
    const float* b_embed  = (const float*)d_in[3];
    const float* conv_W   = (const float*)d_in[4];
    const float* conv_b   = (const float*)d_in[5];
    const float* conv_g1  = (const float*)d_in[6];
    const float* conv_be1 = (const float*)d_in[7];
    const float* conv_g2  = (const float*)d_in[8];
    const float* conv_be2 = (const float*)d_in[9];
    const float* head_W1  = (const float*)d_in[10];
    const float* head_b1  = (const float*)d_in[11];
    const float* head_W2  = (const float*)d_in[12];
    const float* head_b2  = (const float*)d_in[13];
    const int*   nbr_idx  = (const int*)d_in[14];
    const int*   cidx     = (const int*)d_in[15];
    float* out = (float*)d_out;

    cudaFuncSetAttribute(k_stats, cudaFuncAttributeMaxDynamicSharedMemorySize, DSMEM);

    k_embed<<<2048, 128>>>(atom_fea, W_embed, b_embed);
    for (int l = 0; l < NCONV; l++) {
        k_proj  <<<2048, 256>>>(conv_W, conv_b, l, l > 0);
        k_stats <<<NB, 128, DSMEM>>>(nbr_fea, nbr_idx, conv_W,
                                     conv_g1, conv_be1, l);
        k_act   <<<NB2, 256>>>(conv_g2, conv_be2, l);
    }
    k_finish<<<NSEG, HDIM>>>(cidx, head_W1, head_b1, head_W2, head_b2,
                             out, out + NSEG*NPROP);
}

// round 14
// speedup vs baseline: 1.0123x; 1.0123x over previous
#include <cuda_runtime.h>
#include <cuda_bf16.h>
#include <cstdint>

#define NATOMS 131072
#define MNBR   12
#define ORIG   92
#define NBRF   41
#define AF     64
#define HDIM   128
#define NPROP  2
#define NCONV  3
#define NSEG   1024
#define FIN    169
#define C2     128
#define EPSBN  1e-5f

#define NPAIR  (NATOMS*MNBR)           // 1572864
#define TILE   48                      // 4 atoms x 12 nbrs
#define NTILE  (NPAIR/TILE)            // 32768
#define NB     592                     // 148 SMs x 4 resident blocks

// conv-pass dynamic smem (double buffered)
#define A_BYTES (TILE*NBRF*4)          // 7872
#define A_CHUNK (A_BYTES/16)           // 492
#define T_OFF   A_BYTES                // bf16 rows: 256B data padded to 272B
#define TROWB   272
#define T_BYTES (TILE*TROWB)           // 13056
#define S_OFF   (T_OFF + T_BYTES)      // bf16 rows (bias pre-added): 272B
#define SROWB   272
#define S_BYTES (4*SROWB)              // 1088
#define BUFSZ   (S_OFF + S_BYTES)      // 22016
#define DSMEM   (2*BUFSZ)              // 44032

// channel base for warp w, n-tile nt: filter (nt 0,1) then core partner (+64)
#define CHBASE(w, nt) ((w)*16 + ((nt)&1)*8 + ((nt)>>1)*64)

// ---------------- scratch ----------------------------------------------------
__device__ float g_x[(size_t)NATOMS*AF];
__device__ __nv_bfloat16 g_S[(size_t)NATOMS*C2];   // 33.5 MB, bf16, bias folded
__device__ __nv_bfloat16 g_T[(size_t)NATOMS*C2];   // 33.5 MB, bf16
__device__ float g_nbrsum[(size_t)NATOMS*AF];
__device__ float g_part1[1024*C2];
__device__ float g_part2[1024*C2];
__device__ float g_partA[1024*AF];
__device__ float g_partB[1024*AF];
__device__ float g_scale1[C2], g_shift1[C2];
__device__ float g_scale2[AF], g_shift2[AF];
__device__ unsigned g_c1 = 0, g_c2 = 0;

// ---------------- helpers ----------------------------------------------------
__device__ __forceinline__ float sp(float x) {
    return fmaxf(x, 0.f) + __logf(1.f + __expf(-fabsf(x)));
}
__device__ __forceinline__ float sig(float x) {
    return 1.f / (1.f + __expf(-x));
}
__device__ __forceinline__ int lbound(const int* __restrict__ a, int n, int v) {
    int lo = 0, hi = n;
    while (lo < hi) { int mid = (lo + hi) >> 1; if (a[mid] < v) lo = mid + 1; else hi = mid; }
    return lo;
}
__device__ __forceinline__ unsigned f2tf32(float v) {
    unsigned u; asm("cvt.rna.tf32.f32 %0, %1;" : "=r"(u) : "f"(v)); return u;
}
__device__ __forceinline__ void cp16(uint32_t dst, const void* src) {
    asm volatile("cp.async.cg.shared.global [%0], [%1], 16;\n" :: "r"(dst), "l"(src));
}
__device__ __forceinline__ void cp_commit() {
    asm volatile("cp.async.commit_group;\n");
}
__device__ __forceinline__ float bfly3(float v) {
    v += __shfl_xor_sync(0xffffffffu, v, 4);
    v += __shfl_xor_sync(0xffffffffu, v, 8);
    v += __shfl_xor_sync(0xffffffffu, v, 16);
    return v;
}
__device__ __forceinline__ float2 ldbf2(const char* p) {
    __nv_bfloat162 h = *(const __nv_bfloat162*)p;
    return __bfloat1622float2(h);
}

#define MMA_TF32(cr, a0, a1, a2, a3, b0, b1) \
    asm("mma.sync.aligned.m16n8k8.row.col.f32.tf32.tf32.f32 " \
        "{%0,%1,%2,%3}, {%4,%5,%6,%7}, {%8,%9}, {%0,%1,%2,%3};" \
        : "+f"(cr[0]), "+f"(cr[1]), "+f"(cr[2]), "+f"(cr[3]) \
        : "r"(a0), "r"(a1), "r"(a2), "r"(a3), "r"(b0), "r"(b1));

// ---------------- embed: x = atom_fea @ W_embed + b (tf32 MMA) ---------------
__global__ void __launch_bounds__(128) k_embed(const float* __restrict__ af,
        const float* __restrict__ W, const float* __restrict__ b) {
    int tid = threadIdx.x, warp = tid >> 5, lane = tid & 31;
    int gr = lane >> 2, gc = lane & 3;
    unsigned bfr[12][2][2];
    #pragma unroll
    for (int ks = 0; ks < 12; ks++)
        #pragma unroll
        for (int nt = 0; nt < 2; nt++) {
            int c = warp*16 + nt*8 + gr;
            int k0 = ks*8 + gc, k1 = k0 + 4;
            bfr[ks][nt][0] = f2tf32((k0 < ORIG) ? W[k0*AF + c] : 0.f);
            bfr[ks][nt][1] = f2tf32((k1 < ORIG) ? W[k1*AF + c] : 0.f);
        }
    __shared__ unsigned Ash[32*100];
    __shared__ float Csh[32*68];
    for (int tt = 0; tt < 2; tt++) {
        int t = blockIdx.x + tt*2048;
        int a0 = t*32;
        for (int i = tid; i < 32*100; i += 128) {
            int r = i/100, k = i - r*100;
            float v = (k < ORIG) ? af[(size_t)(a0+r)*ORIG + k] : 0.f;
            Ash[i] = f2tf32(v);
        }
        __syncthreads();
        #pragma unroll
        for (int mt = 0; mt < 2; mt++) {
            float cr[2][4] = {};
            #pragma unroll
            for (int ks = 0; ks < 12; ks++) {
                unsigned a0f = Ash[(mt*16+gr)*100   + ks*8+gc];
                unsigned a1f = Ash[(mt*16+gr+8)*100 + ks*8+gc];
                unsigned a2f = Ash[(mt*16+gr)*100   + ks*8+gc+4];
                unsigned a3f = Ash[(mt*16+gr+8)*100 + ks*8+gc+4];
                #pragma unroll
                for (int nt = 0; nt < 2; nt++)
                    MMA_TF32(cr[nt], a0f, a1f, a2f, a3f, bfr[ks][nt][0], bfr[ks][nt][1]);
            }
            #pragma unroll
            for (int nt = 0; nt < 2; nt++) {
                int cb = warp*16 + nt*8 + gc*2;
                Csh[(mt*16+gr)*68   + cb]   = cr[nt][0];
                Csh[(mt*16+gr)*68   + cb+1] = cr[nt][1];
                Csh[(mt*16+gr+8)*68 + cb]   = cr[nt][2];
                Csh[(mt*16+gr+8)*68 + cb+1] = cr[nt][3];
            }
        }
        __syncthreads();
        #pragma unroll
        for (int i = 0; i < 4; i++) {
            int lin = tid + i*128;
            int r = lin >> 4, c4 = lin & 15;
            float4 v = *(float4*)&Csh[r*68 + c4*4];
            float4 bi = *(const float4*)&b[c4*4];
            v.x += bi.x; v.y += bi.y; v.z += bi.z; v.w += bi.w;
            *(float4*)&g_x[(size_t)(a0+r)*AF + c4*4] = v;
        }
        __syncthreads();
    }
}

// ---------------- proj: [S|T] = x @ W[0:128,:]; bias folded, bf16 out --------
__global__ void __launch_bounds__(256) k_proj(const float* __restrict__ convW,
        const float* __restrict__ convB, int l, int fuse) {
    const float* W = convW + (size_t)l*FIN*C2;
    int tid = threadIdx.x, warp = tid >> 5, lane = tid & 31;
    int gr = lane >> 2, gc = lane & 3;
    int isT = (warp >= 4), w4 = warp & 3;
    int rbase = isT ? AF : 0;
    unsigned bfr[8][4][2];
    #pragma unroll
    for (int ks = 0; ks < 8; ks++)
        #pragma unroll
        for (int nt = 0; nt < 4; nt++) {
            int c = w4*32 + nt*8 + gr;
            int k0 = ks*8 + gc, k1 = k0 + 4;
            bfr[ks][nt][0] = f2tf32(W[(rbase+k0)*C2 + c]);
            bfr[ks][nt][1] = f2tf32(W[(rbase+k1)*C2 + c]);
        }
    __shared__ unsigned Ash[32*68];
    __shared__ float Csh[32*264];
    for (int tt = 0; tt < 2; tt++) {
        int t = blockIdx.x + tt*2048;
        int a0 = t*32;
        {
            int r = tid >> 3, q = tid & 7;
            size_t base = (size_t)(a0+r)*AF + q*8;
            float4 v0 = *(const float4*)&g_x[base];
            float4 v1 = *(const float4*)&g_x[base+4];
            if (fuse) {
                float4 n0 = *(const float4*)&g_nbrsum[base];
                float4 n1 = *(const float4*)&g_nbrsum[base+4];
                float4 sc0 = *(const float4*)&g_scale2[q*8];
                float4 sc1 = *(const float4*)&g_scale2[q*8+4];
                float4 sh0 = *(const float4*)&g_shift2[q*8];
                float4 sh1 = *(const float4*)&g_shift2[q*8+4];
                v0.x = sp(v0.x + n0.x*sc0.x + sh0.x);
                v0.y = sp(v0.y + n0.y*sc0.y + sh0.y);
                v0.z = sp(v0.z + n0.z*sc0.z + sh0.z);
                v0.w = sp(v0.w + n0.w*sc0.w + sh0.w);
                v1.x = sp(v1.x + n1.x*sc1.x + sh1.x);
                v1.y = sp(v1.y + n1.y*sc1.y + sh1.y);
                v1.z = sp(v1.z + n1.z*sc1.z + sh1.z);
                v1.w = sp(v1.w + n1.w*sc1.w + sh1.w);
                *(float4*)&g_x[base]   = v0;
                *(float4*)&g_x[base+4] = v1;
            }
            unsigned* dst = &Ash[r*68 + q*8];
            dst[0]=f2tf32(v0.x); dst[1]=f2tf32(v0.y); dst[2]=f2tf32(v0.z); dst[3]=f2tf32(v0.w);
            dst[4]=f2tf32(v1.x); dst[5]=f2tf32(v1.y); dst[6]=f2tf32(v1.z); dst[7]=f2tf32(v1.w);
        }
        __syncthreads();
        #pragma unroll
        for (int mt = 0; mt < 2; mt++) {
            float cr[4][4] = {};
            #pragma unroll
            for (int ks = 0; ks < 8; ks++) {
                unsigned a0f = Ash[(mt*16+gr)*68   + ks*8+gc];
                unsigned a1f = Ash[(mt*16+gr+8)*68 + ks*8+gc];
                unsigned a2f = Ash[(mt*16+gr)*68   + ks*8+gc+4];
                unsigned a3f = Ash[(mt*16+gr+8)*68 + ks*8+gc+4];
                #pragma unroll
                for (int nt = 0; nt < 4; nt++)
                    MMA_TF32(cr[nt], a0f, a1f, a2f, a3f, bfr[ks][nt][0], bfr[ks][nt][1]);
            }
            #pragma unroll
            for (int nt = 0; nt < 4; nt++) {
                int cb = (isT ? 132 : 0) + w4*32 + nt*8 + gc*2;
                Csh[(mt*16+gr)*264   + cb]   = cr[nt][0];
                Csh[(mt*16+gr)*264   + cb+1] = cr[nt][1];
                Csh[(mt*16+gr+8)*264 + cb]   = cr[nt][2];
                Csh[(mt*16+gr+8)*264 + cb+1] = cr[nt][3];
            }
        }
        __syncthreads();
        // S: bf16 with bias folded in (fp32 add, then round)
        #pragma unroll
        for (int i = 0; i < 2; i++) {
            int lin = tid + i*256;
            int r = lin >> 4, c8 = lin & 15;
            const float* src = &Csh[r*264 + c8*8];
            const float* bia = &convB[l*C2 + c8*8];
            float4 v0 = *(const float4*)src, v1 = *(const float4*)(src+4);
            float4 b0 = *(const float4*)bia, b1 = *(const float4*)(bia+4);
            __nv_bfloat162 h0 = __float22bfloat162_rn(make_float2(v0.x+b0.x, v0.y+b0.y));
            __nv_bfloat162 h1 = __float22bfloat162_rn(make_float2(v0.z+b0.z, v0.w+b0.w));
            __nv_bfloat162 h2 = __float22bfloat162_rn(make_float2(v1.x+b1.x, v1.y+b1.y));
            __nv_bfloat162 h3 = __float22bfloat162_rn(make_float2(v1.z+b1.z, v1.w+b1.w));
            uint4 pk;
            pk.x = *(unsigned*)&h0; pk.y = *(unsigned*)&h1;
            pk.z = *(unsigned*)&h2; pk.w = *(unsigned*)&h3;
            *(uint4*)((char*)g_S + (size_t)(a0+r)*256 + c8*16) = pk;
        }
        // T: bf16 (32 rows x 256B)
        #pragma unroll
        for (int i = 0; i < 2; i++) {
            int lin = tid + i*256;
            int r = lin >> 4, c8 = lin & 15;
            const float* src = &Csh[r*264 + 132 + c8*8];
            float4 v0 = *(const float4*)src, v1 = *(const float4*)(src+4);
            __nv_bfloat162 h0 = __float22bfloat162_rn(make_float2(v0.x, v0.y));
            __nv_bfloat162 h1 = __float22bfloat162_rn(make_float2(v0.z, v0.w));
            __nv_bfloat162 h2 = __float22bfloat162_rn(make_float2(v1.x, v1.y));
            __nv_bfloat162 h3 = __float22bfloat162_rn(make_float2(v1.z, v1.w));
            uint4 pk;
            pk.x = *(unsigned*)&h0; pk.y = *(unsigned*)&h1;
            pk.z = *(unsigned*)&h2; pk.w = *(unsigned*)&h3;
            *(uint4*)((char*)g_T + (size_t)(a0+r)*256 + c8*16) = pk;
        }
        __syncthreads();
    }
}

// ======= conv pass machinery (4 warps, 32 ch/warp) ===========================
__device__ __forceinline__ void prefetch_tile(int t, uint32_t bb,
        const float* __restrict__ nbr_fea, const int* __restrict__ idx, int tid) {
    const char* asrc = (const char*)nbr_fea + (size_t)t * A_BYTES;
    #pragma unroll
    for (int i = 0; i < 4; i++) {
        int c = tid + i*128;
        if (c < A_CHUNK) cp16(bb + c*16, asrc + c*16);
    }
    int p0 = t * TILE;
    #pragma unroll
    for (int i = 0; i < 6; i++) {               // bf16 T rows: 256B each
        int lin = tid + i*128;
        int r = lin >> 4, cx = lin & 15;
        int j = __ldg(&idx[p0 + r]);
        cp16(bb + T_OFF + r*TROWB + cx*16, (const char*)g_T + ((size_t)j << 8) + cx*16);
    }
    if (tid < 64) {                              // bf16 S rows: 256B each
        int r = tid >> 4, cx = tid & 15;
        cp16(bb + S_OFF + r*SROWB + cx*16,
             (const char*)g_S + ((size_t)(t*4 + r) << 8) + cx*16);
    }
    cp_commit();
}

#define PASS_PROLOG \
    const float* W3 = convW + (size_t)l*FIN*C2 + (size_t)C2*C2;                 \
    int tid  = threadIdx.x;                                                     \
    int warp = tid >> 5, lane = tid & 31;                                       \
    int gr = lane >> 2, gc = lane & 3;                                          \
    unsigned bfr[5][4][2];                                                      \
    _Pragma("unroll") for (int ks = 0; ks < 5; ks++)                            \
        _Pragma("unroll") for (int nt = 0; nt < 4; nt++) {                      \
            int c  = CHBASE(warp, nt) + gr;                                     \
            int k0 = ks*8 + gc, k1 = k0 + 4;                                    \
            bfr[ks][nt][0] = f2tf32(W3[k0*C2 + c]);                             \
            bfr[ks][nt][1] = f2tf32(W3[k1*C2 + c]);                             \
        }                                                                       \
    float w40[4][2];                                                            \
    _Pragma("unroll") for (int nt = 0; nt < 4; nt++) {                          \
        w40[nt][0] = W3[40*C2 + CHBASE(warp, nt) + gc*2];                       \
        w40[nt][1] = W3[40*C2 + CHBASE(warp, nt) + gc*2 + 1];                   \
    }                                                                           \
    extern __shared__ char smx[];                                               \
    uint32_t sbase = (uint32_t)__cvta_generic_to_shared(smx);

// MMA over k=0..39 (tf32), then k=40 via fp32 FFMA (identical in both passes).
#define DO_MMA(mt, cr, Au, Af) \
        _Pragma("unroll") for (int ks = 0; ks < 5; ks++) {                      \
            unsigned a0 = Au[((mt)*16+gr)*NBRF   + ks*8+gc];                    \
            unsigned a1 = Au[((mt)*16+gr+8)*NBRF + ks*8+gc];                    \
            unsigned a2 = Au[((mt)*16+gr)*NBRF   + ks*8+gc+4];                  \
            unsigned a3 = Au[((mt)*16+gr+8)*NBRF + ks*8+gc+4];                  \
            _Pragma("unroll") for (int nt = 0; nt < 4; nt++)                    \
                MMA_TF32(cr[nt], a0, a1, a2, a3, bfr[ks][nt][0], bfr[ks][nt][1]); \
        }                                                                       \
        {   float a40_0 = Af[((mt)*16+gr)*NBRF + 40];                           \
            float a40_1 = Af[((mt)*16+gr+8)*NBRF + 40];                         \
            _Pragma("unroll") for (int nt = 0; nt < 4; nt++) {                  \
                cr[nt][0] += a40_0*w40[nt][0];  cr[nt][1] += a40_0*w40[nt][1];  \
                cr[nt][2] += a40_1*w40[nt][0];  cr[nt][3] += a40_1*w40[nt][1];  \
            }                                                                   \
        }

// ---------------- pass 1: BN1 statistics + fused reduce ----------------------
__global__ void __launch_bounds__(128, 4) k_stats(const float* __restrict__ nbr_fea,
        const int* __restrict__ idx, const float* __restrict__ convW,
        const float* __restrict__ g1, const float* __restrict__ be1, int l) {
    PASS_PROLOG
    float sch[4][2] = {}, sch2[4][2] = {};
    int t = blockIdx.x;
    prefetch_tile(t, sbase, nbr_fea, idx, tid);
    int cur = 0;
    for (; t < NTILE; t += NB) {
        int tn = t + NB;
        if (tn < NTILE) {
            prefetch_tile(tn, sbase + (1-cur)*BUFSZ, nbr_fea, idx, tid);
            asm volatile("cp.async.wait_group 1;\n");
        } else {
            asm volatile("cp.async.wait_group 0;\n");
        }
        __syncthreads();
        const unsigned* Au = (const unsigned*)(smx + cur*BUFSZ);
        const float*    Af = (const float*)(smx + cur*BUFSZ);
        const char*     TB = smx + cur*BUFSZ + T_OFF;
        const char*     SB = smx + cur*BUFSZ + S_OFF;
        #pragma unroll
        for (int mt = 0; mt < 3; mt++) {
            float cr[4][4] = {};
            DO_MMA(mt, cr, Au, Af)
            int r0 = mt*16 + gr, r1 = r0 + 8;
            int a0i = r0 / MNBR, a1i = r1 / MNBR;
            #pragma unroll
            for (int nt = 0; nt < 4; nt++) {
                int c0 = CHBASE(warp, nt) + gc*2;
                float2 t0 = ldbf2(TB + r0*TROWB + c0*2);
                float2 s0 = ldbf2(SB + a0i*SROWB + c0*2);
                float2 t1 = ldbf2(TB + r1*TROWB + c0*2);
                float2 s1 = ldbf2(SB + a1i*SROWB + c0*2);
                float v;
                v = cr[nt][0] + t0.x + s0.x; sch[nt][0] += v; sch2[nt][0] += v*v;
                v = cr[nt][1] + t0.y + s0.y; sch[nt][1] += v; sch2[nt][1] += v*v;
                v = cr[nt][2] + t1.x + s1.x; sch[nt][0] += v; sch2[nt][0] += v*v;
                v = cr[nt][3] + t1.y + s1.y; sch[nt][1] += v; sch2[nt][1] += v*v;
            }
        }
        __syncthreads();
        cur ^= 1;
    }
    #pragma unroll
    for (int nt = 0; nt < 4; nt++)
        #pragma unroll
        for (int j = 0; j < 2; j++) {
            sch[nt][j]  = bfly3(sch[nt][j]);
            sch2[nt][j] = bfly3(sch2[nt][j]);
        }
    if (lane < 4) {
        #pragma unroll
        for (int nt = 0; nt < 4; nt++)
            #pragma unroll
            for (int j = 0; j < 2; j++) {
                int c = CHBASE(warp, nt) + lane*2 + j;
                g_part1[blockIdx.x*C2 + c] = sch[nt][j];
                g_part2[blockIdx.x*C2 + c] = sch2[nt][j];
            }
    }
    __shared__ int amLast;
    __threadfence();
    __syncthreads();
    if (tid == 0) amLast = (atomicAdd(&g_c1, 1u) == NB - 1);
    __syncthreads();
    if (amLast) {
        int c = tid;
        float s = 0.f, s2 = 0.f;
        for (int i = 0; i < NB; i++) {
            s += g_part1[i*C2 + c]; s2 += g_part2[i*C2 + c];
        }
        float cnt  = (float)((size_t)NATOMS * MNBR);
        float mean = s / cnt;
        float var  = s2 / cnt - mean*mean;
        float rstd = rsqrtf(var + EPSBN);
        float sc   = g1[l*C2 + c] * rstd;
        g_scale1[c] = sc;
        g_shift1[c] = be1[l*C2 + c] - mean*sc;
        if (tid == 0) g_c1 = 0;
    }
}

// ---------------- pass 2: recompute + activation + shfl nbr-sum + fused BN2 --
__global__ void __launch_bounds__(128, 4) k_conv(const float* __restrict__ nbr_fea,
        const int* __restrict__ idx, const float* __restrict__ convW,
        const float* __restrict__ g2, const float* __restrict__ be2, int l) {
    PASS_PROLOG
    float scF[2][2], shF[2][2], scC[2][2], shC[2][2];
    #pragma unroll
    for (int nt = 0; nt < 2; nt++)
        #pragma unroll
        for (int j = 0; j < 2; j++) {
            int cF0 = CHBASE(warp, nt) + gc*2 + j;
            scF[nt][j] = g_scale1[cF0];      shF[nt][j] = g_shift1[cF0];
            scC[nt][j] = g_scale1[cF0+64];   shC[nt][j] = g_shift1[cF0+64];
        }
    float sAc[2][2] = {}, sAc2[2][2] = {};

    int t = blockIdx.x;
    prefetch_tile(t, sbase, nbr_fea, idx, tid);
    int cur = 0;
    for (; t < NTILE; t += NB) {
        int tn = t + NB;
        if (tn < NTILE) {
            prefetch_tile(tn, sbase + (1-cur)*BUFSZ, nbr_fea, idx, tid);
            asm volatile("cp.async.wait_group 1;\n");
        } else {
            asm volatile("cp.async.wait_group 0;\n");
        }
        __syncthreads();
        const unsigned* Au = (const unsigned*)(smx + cur*BUFSZ);
        const float*    Af = (const float*)(smx + cur*BUFSZ);
        const char*     TB = smx + cur*BUFSZ + T_OFF;
        const char*     SB = smx + cur*BUFSZ + S_OFF;
        float P[4][2][2] = {};          // atom x nt x j partials (static indices)
        #pragma unroll
        for (int mt = 0; mt < 3; mt++) {
            float cr[4][4] = {};
            DO_MMA(mt, cr, Au, Af)
            #pragma unroll
            for (int rr = 0; rr < 2; rr++) {
                const int slot = mt*2 + rr;            // rows [slot*8, slot*8+8)
                const int alo = (slot*8) / MNBR;
                const int ahi = (slot*8 + 7) / MNBR;
                int r  = slot*8 + gr;
                int ai = (alo == ahi) ? alo : ((gr < 4) ? alo : ahi);
                #pragma unroll
                for (int nt = 0; nt < 2; nt++) {
                    int cF = CHBASE(warp, nt) + gc*2;
                    int cC = cF + 64;
                    float2 tF = ldbf2(TB + r*TROWB + cF*2);
                    float2 sF = ldbf2(SB + ai*SROWB + cF*2);
                    float2 tC = ldbf2(TB + r*TROWB + cC*2);
                    float2 sC = ldbf2(SB + ai*SROWB + cC*2);
                    float F0 = cr[nt][rr*2]     + tF.x + sF.x;
                    float F1 = cr[nt][rr*2+1]   + tF.y + sF.y;
                    float C0 = cr[nt+2][rr*2]   + tC.x + sC.x;
                    float C1 = cr[nt+2][rr*2+1] + tC.y + sC.y;
                    float a0v = sig(F0*scF[nt][0] + shF[nt][0]) * sp(C0*scC[nt][0] + shC[nt][0]);
                    float a1v = sig(F1*scF[nt][1] + shF[nt][1]) * sp(C1*scC[nt][1] + shC[nt][1]);
                    if (alo == ahi) {
                        P[alo][nt][0] += a0v; P[alo][nt][1] += a1v;
                    } else if (gr < 4) {
                        P[alo][nt][0] += a0v; P[alo][nt][1] += a1v;
                    } else {
                        P[ahi][nt][0] += a0v; P[ahi][nt][1] += a1v;
                    }
                }
            }
        }
        // butterfly over gr lanes -> every lane holds full 12-neighbor sums
        #pragma unroll
        for (int a = 0; a < 4; a++)
            #pragma unroll
            for (int nt = 0; nt < 2; nt++)
                #pragma unroll
                for (int j = 0; j < 2; j++)
                    P[a][nt][j] = bfly3(P[a][nt][j]);
        // lane gr==a stores atom a; accumulate BN2 partials
        #pragma unroll
        for (int a = 0; a < 4; a++) {
            if (gr == a) {
                #pragma unroll
                for (int nt = 0; nt < 2; nt++) {
                    float2 st = make_float2(P[a][nt][0], P[a][nt][1]);
                    *(float2*)&g_nbrsum[(size_t)(t*4 + a)*AF + CHBASE(warp, nt) + gc*2] = st;
                    #pragma unroll
                    for (int j = 0; j < 2; j++) {
                        sAc[nt][j]  += P[a][nt][j];
                        sAc2[nt][j] += P[a][nt][j]*P[a][nt][j];
                    }
                }
            }
        }
        __syncthreads();
        cur ^= 1;
    }
    #pragma unroll
    for (int nt = 0; nt < 2; nt++)
        #pragma unroll
        for (int j = 0; j < 2; j++) {
            sAc[nt][j]  = bfly3(sAc[nt][j]);
            sAc2[nt][j] = bfly3(sAc2[nt][j]);
        }
    if (lane < 4) {
        #pragma unroll
        for (int nt = 0; nt < 2; nt++)
            #pragma unroll
            for (int j = 0; j < 2; j++) {
                int c = CHBASE(warp, nt) + lane*2 + j;
                g_partA[blockIdx.x*AF + c] = sAc[nt][j];
                g_partB[blockIdx.x*AF + c] = sAc2[nt][j];
            }
    }
    // fused BN2 reduce
    __shared__ int amLast;
    __threadfence();
    __syncthreads();
    if (tid == 0) amLast = (atomicAdd(&g_c2, 1u) == NB - 1);
    __syncthreads();
    if (amLast && tid < AF) {
        int c = tid;
        float s = 0.f, s2 = 0.f;
        for (int i = 0; i < NB; i++) {
            s += g_partA[i*AF + c]; s2 += g_partB[i*AF + c];
        }
        float cnt  = (float)NATOMS;
        float mean = s / cnt;
        float var  = s2 / cnt - mean*mean;
        float rstd = rsqrtf(var + EPSBN);
        float sc   = g2[l*AF + c] * rstd;
        g_scale2[c] = sc;
        g_shift2[c] = be2[l*AF + c] - mean*sc;
        if (tid == 0) g_c2 = 0;
    }
}

// ---------------- finish: final update + segment mean pool + MLP head --------
__global__ void __launch_bounds__(128) k_finish(const int* __restrict__ cidx,
        const float* __restrict__ W1, const float* __restrict__ b1,
        const float* __restrict__ W2, const float* __restrict__ b2,
        float* __restrict__ out, float* __restrict__ out_crys) {
    int b = blockIdx.x, tid = threadIdx.x;
    int lo = lbound(cidx, NATOMS, b);
    int hi = lbound(cidx, NATOMS, b + 1);
    int f = tid & 63, half = tid >> 6;
    float sc2 = g_scale2[f], sh2v = g_shift2[f];
    float s = 0.f;
    for (int a = lo + half; a < hi; a += 2) {
        size_t i = (size_t)a*AF + f;
        s += sp(g_x[i] + g_nbrsum[i]*sc2 + sh2v);
    }
    __shared__ float psum[2][AF];
    __shared__ float av[AF];
    __shared__ float red[HDIM];
    psum[half][f] = s;
    __syncthreads();
    if (tid < AF) {
        float v = (psum[0][tid] + psum[1][tid]) / fmaxf((float)(hi - lo), 1.f);
        out_crys[b*AF + tid] = v;
        av[tid] = sp(v);
    }
    __syncthreads();
    for (int p = 0; p < NPROP; p++) {
        float acc = b1[p*HDIM + tid];
        #pragma unroll
        for (int k = 0; k < AF; k++) acc += av[k] * W1[((size_t)p*AF + k)*HDIM + tid];
        red[tid] = sp(acc) * W2[p*HDIM + tid];
        __syncthreads();
        for (int o = 64; o > 0; o >>= 1) {
            if (tid < o) red[tid] += red[tid+o];
            __syncthreads();
        }
        if (tid == 0) out[b*NPROP + p] = red[0] + b2[p];
        __syncthreads();
    }
}

// ---------------- launch --------------------------------------------------------
extern "C" void kernel_launch(void* const* d_in, const int* in_sizes, int n_in,
                              void* d_out, int out_size) {
    const float* atom_fea = (const float*)d_in[0];
    const float* nbr_fea  = (const float*)d_in[1];
    const float* W_embed  = (const float*)d_in[2];
    const float* b_embed  = (const float*)d_in[3];
    const float* conv_W   = (const float*)d_in[4];
    const float* conv_b   = (const float*)d_in[5];
    const float* conv_g1  = (const float*)d_in[6];
    const float* conv_be1 = (const float*)d_in[7];
    const float* conv_g2  = (const float*)d_in[8];
    const float* conv_be2 = (const float*)d_in[9];
    const float* head_W1  = (const float*)d_in[10];
    const float* head_b1  = (const float*)d_in[11];
    const float* head_W2  = (const float*)d_in[12];
    const float* head_b2  = (const float*)d_in[13];
    const int*   nbr_idx  = (const int*)d_in[14];
    const int*   cidx     = (const int*)d_in[15];
    float* out = (float*)d_out;

    cudaFuncSetAttribute(k_stats, cudaFuncAttributeMaxDynamicSharedMemorySize, DSMEM);
    cudaFuncSetAttribute(k_conv,  cudaFuncAttributeMaxDynamicSharedMemorySize, DSMEM);

    k_embed<<<2048, 128>>>(atom_fea, W_embed, b_embed);
    for (int l = 0; l < NCONV; l++) {
        k_proj  <<<2048, 256>>>(conv_W, conv_b, l, l > 0);
        k_stats <<<NB, 128, DSMEM>>>(nbr_fea, nbr_idx, conv_W,
                                     conv_g1, conv_be1, l);
        k_conv  <<<NB, 128, DSMEM>>>(nbr_fea, nbr_idx, conv_W,
                                     conv_g2, conv_be2, l);
    }
    k_finish<<<NSEG, HDIM>>>(cidx, head_W1, head_b1, head_W2, head_b2,
                             out, out + NSEG*NPROP);
}

// round 15
// speedup vs baseline: 1.1575x; 1.1435x over previous
#include <cuda_runtime.h>
#include <cuda_bf16.h>
#include <cstdint>

#define NATOMS 131072
#define MNBR   12
#define ORIG   92
#define NBRF   41
#define AF     64
#define HDIM   128
#define NPROP  2
#define NCONV  3
#define NSEG   1024
#define FIN    169
#define C2     128
#define EPSBN  1e-5f

#define NPAIR  (NATOMS*MNBR)           // 1572864
#define TILE   48                      // 4 atoms x 12 nbrs
#define NTILE  (NPAIR/TILE)            // 32768
#define NB     592                     // 148 SMs x 4 resident blocks

// conv-pass dynamic smem (double buffered)
#define A_BYTES (TILE*NBRF*4)          // 7872
#define A_CHUNK (A_BYTES/16)           // 492
#define T_OFF   A_BYTES                // bf16 rows: 256B data padded to 272B
#define TROWB   272
#define T_BYTES (TILE*TROWB)           // 13056
#define S_OFF   (T_OFF + T_BYTES)      // fp32 rows padded: 528B (bias folded)
#define SROW    132
#define S_BYTES (4*SROW*4)             // 2112
#define BUFSZ   (S_OFF + S_BYTES)      // 23040
#define DSMEM   (2*BUFSZ)              // 46080

// channel base for warp w, n-tile nt: filter (nt 0,1) then core partner (+64)
#define CHBASE(w, nt) ((w)*16 + ((nt)&1)*8 + ((nt)>>1)*64)

// ---------------- scratch ----------------------------------------------------
__device__ float g_x[(size_t)NATOMS*AF];
__device__ float g_S[(size_t)NATOMS*C2];           // fp32, bias folded in
__device__ __nv_bfloat16 g_T[(size_t)NATOMS*C2];   // 33.5 MB, bf16
__device__ float g_nbrsum[(size_t)NATOMS*AF];
__device__ float g_part1[1024*C2];
__device__ float g_part2[1024*C2];
__device__ float g_partA[1024*AF];
__device__ float g_partB[1024*AF];
__device__ float g_scale1[C2], g_shift1[C2];
__device__ float g_scale2[AF], g_shift2[AF];
__device__ unsigned g_c1 = 0, g_c2 = 0;

// ---------------- helpers ----------------------------------------------------
__device__ __forceinline__ float sp(float x) {
    return fmaxf(x, 0.f) + __logf(1.f + __expf(-fabsf(x)));
}
// sigmoid via hardware tanh: 1 MUFU instead of EX2+RCP
__device__ __forceinline__ float sigt(float x) {
    float t;
    asm("tanh.approx.f32 %0, %1;" : "=f"(t) : "f"(x*0.5f));
    return fmaf(0.5f, t, 0.5f);
}
__device__ __forceinline__ int lbound(const int* __restrict__ a, int n, int v) {
    int lo = 0, hi = n;
    while (lo < hi) { int mid = (lo + hi) >> 1; if (a[mid] < v) lo = mid + 1; else hi = mid; }
    return lo;
}
__device__ __forceinline__ unsigned f2tf32(float v) {
    unsigned u; asm("cvt.rna.tf32.f32 %0, %1;" : "=r"(u) : "f"(v)); return u;
}
__device__ __forceinline__ void cp16(uint32_t dst, const void* src) {
    asm volatile("cp.async.cg.shared.global [%0], [%1], 16;\n" :: "r"(dst), "l"(src));
}
__device__ __forceinline__ void cp_commit() {
    asm volatile("cp.async.commit_group;\n");
}
__device__ __forceinline__ float bfly3(float v) {
    v += __shfl_xor_sync(0xffffffffu, v, 4);
    v += __shfl_xor_sync(0xffffffffu, v, 8);
    v += __shfl_xor_sync(0xffffffffu, v, 16);
    return v;
}
__device__ __forceinline__ float2 ldbf2(const char* p) {
    __nv_bfloat162 h = *(const __nv_bfloat162*)p;
    return __bfloat1622float2(h);
}

#define MMA_TF32(cr, a0, a1, a2, a3, b0, b1) \
    asm("mma.sync.aligned.m16n8k8.row.col.f32.tf32.tf32.f32 " \
        "{%0,%1,%2,%3}, {%4,%5,%6,%7}, {%8,%9}, {%0,%1,%2,%3};" \
        : "+f"(cr[0]), "+f"(cr[1]), "+f"(cr[2]), "+f"(cr[3]) \
        : "r"(a0), "r"(a1), "r"(a2), "r"(a3), "r"(b0), "r"(b1));

// ---------------- embed: x = atom_fea @ W_embed + b (tf32 MMA) ---------------
__global__ void __launch_bounds__(128) k_embed(const float* __restrict__ af,
        const float* __restrict__ W, const float* __restrict__ b) {
    int tid = threadIdx.x, warp = tid >> 5, lane = tid & 31;
    int gr = lane >> 2, gc = lane & 3;
    unsigned bfr[12][2][2];
    #pragma unroll
    for (int ks = 0; ks < 12; ks++)
        #pragma unroll
        for (int nt = 0; nt < 2; nt++) {
            int c = warp*16 + nt*8 + gr;
            int k0 = ks*8 + gc, k1 = k0 + 4;
            bfr[ks][nt][0] = f2tf32((k0 < ORIG) ? W[k0*AF + c] : 0.f);
            bfr[ks][nt][1] = f2tf32((k1 < ORIG) ? W[k1*AF + c] : 0.f);
        }
    __shared__ unsigned Ash[32*100];
    __shared__ float Csh[32*68];
    for (int tt = 0; tt < 2; tt++) {
        int t = blockIdx.x + tt*2048;
        int a0 = t*32;
        for (int i = tid; i < 32*100; i += 128) {
            int r = i/100, k = i - r*100;
            float v = (k < ORIG) ? af[(size_t)(a0+r)*ORIG + k] : 0.f;
            Ash[i] = f2tf32(v);
        }
        __syncthreads();
        #pragma unroll
        for (int mt = 0; mt < 2; mt++) {
            float cr[2][4] = {};
            #pragma unroll
            for (int ks = 0; ks < 12; ks++) {
                unsigned a0f = Ash[(mt*16+gr)*100   + ks*8+gc];
                unsigned a1f = Ash[(mt*16+gr+8)*100 + ks*8+gc];
                unsigned a2f = Ash[(mt*16+gr)*100   + ks*8+gc+4];
                unsigned a3f = Ash[(mt*16+gr+8)*100 + ks*8+gc+4];
                #pragma unroll
                for (int nt = 0; nt < 2; nt++)
                    MMA_TF32(cr[nt], a0f, a1f, a2f, a3f, bfr[ks][nt][0], bfr[ks][nt][1]);
            }
            #pragma unroll
            for (int nt = 0; nt < 2; nt++) {
                int cb = warp*16 + nt*8 + gc*2;
                Csh[(mt*16+gr)*68   + cb]   = cr[nt][0];
                Csh[(mt*16+gr)*68   + cb+1] = cr[nt][1];
                Csh[(mt*16+gr+8)*68 + cb]   = cr[nt][2];
                Csh[(mt*16+gr+8)*68 + cb+1] = cr[nt][3];
            }
        }
        __syncthreads();
        #pragma unroll
        for (int i = 0; i < 4; i++) {
            int lin = tid + i*128;
            int r = lin >> 4, c4 = lin & 15;
            float4 v = *(float4*)&Csh[r*68 + c4*4];
            float4 bi = *(const float4*)&b[c4*4];
            v.x += bi.x; v.y += bi.y; v.z += bi.z; v.w += bi.w;
            *(float4*)&g_x[(size_t)(a0+r)*AF + c4*4] = v;
        }
        __syncthreads();
    }
}

// ---------------- proj: [S|T] = x @ W[0:128,:]; bias folded into S (fp32) ----
__global__ void __launch_bounds__(256) k_proj(const float* __restrict__ convW,
        const float* __restrict__ convB, int l, int fuse) {
    const float* W = convW + (size_t)l*FIN*C2;
    int tid = threadIdx.x, warp = tid >> 5, lane = tid & 31;
    int gr = lane >> 2, gc = lane & 3;
    int isT = (warp >= 4), w4 = warp & 3;
    int rbase = isT ? AF : 0;
    unsigned bfr[8][4][2];
    #pragma unroll
    for (int ks = 0; ks < 8; ks++)
        #pragma unroll
        for (int nt = 0; nt < 4; nt++) {
            int c = w4*32 + nt*8 + gr;
            int k0 = ks*8 + gc, k1 = k0 + 4;
            bfr[ks][nt][0] = f2tf32(W[(rbase+k0)*C2 + c]);
            bfr[ks][nt][1] = f2tf32(W[(rbase+k1)*C2 + c]);
        }
    __shared__ unsigned Ash[32*68];
    __shared__ float Csh[32*264];
    for (int tt = 0; tt < 2; tt++) {
        int t = blockIdx.x + tt*2048;
        int a0 = t*32;
        {
            int r = tid >> 3, q = tid & 7;
            size_t base = (size_t)(a0+r)*AF + q*8;
            float4 v0 = *(const float4*)&g_x[base];
            float4 v1 = *(const float4*)&g_x[base+4];
            if (fuse) {
                float4 n0 = *(const float4*)&g_nbrsum[base];
                float4 n1 = *(const float4*)&g_nbrsum[base+4];
                float4 sc0 = *(const float4*)&g_scale2[q*8];
                float4 sc1 = *(const float4*)&g_scale2[q*8+4];
                float4 sh0 = *(const float4*)&g_shift2[q*8];
                float4 sh1 = *(const float4*)&g_shift2[q*8+4];
                v0.x = sp(v0.x + n0.x*sc0.x + sh0.x);
                v0.y = sp(v0.y + n0.y*sc0.y + sh0.y);
                v0.z = sp(v0.z + n0.z*sc0.z + sh0.z);
                v0.w = sp(v0.w + n0.w*sc0.w + sh0.w);
                v1.x = sp(v1.x + n1.x*sc1.x + sh1.x);
                v1.y = sp(v1.y + n1.y*sc1.y + sh1.y);
                v1.z = sp(v1.z + n1.z*sc1.z + sh1.z);
                v1.w = sp(v1.w + n1.w*sc1.w + sh1.w);
                *(float4*)&g_x[base]   = v0;
                *(float4*)&g_x[base+4] = v1;
            }
            unsigned* dst = &Ash[r*68 + q*8];
            dst[0]=f2tf32(v0.x); dst[1]=f2tf32(v0.y); dst[2]=f2tf32(v0.z); dst[3]=f2tf32(v0.w);
            dst[4]=f2tf32(v1.x); dst[5]=f2tf32(v1.y); dst[6]=f2tf32(v1.z); dst[7]=f2tf32(v1.w);
        }
        __syncthreads();
        #pragma unroll
        for (int mt = 0; mt < 2; mt++) {
            float cr[4][4] = {};
            #pragma unroll
            for (int ks = 0; ks < 8; ks++) {
                unsigned a0f = Ash[(mt*16+gr)*68   + ks*8+gc];
                unsigned a1f = Ash[(mt*16+gr+8)*68 + ks*8+gc];
                unsigned a2f = Ash[(mt*16+gr)*68   + ks*8+gc+4];
                unsigned a3f = Ash[(mt*16+gr+8)*68 + ks*8+gc+4];
                #pragma unroll
                for (int nt = 0; nt < 4; nt++)
                    MMA_TF32(cr[nt], a0f, a1f, a2f, a3f, bfr[ks][nt][0], bfr[ks][nt][1]);
            }
            #pragma unroll
            for (int nt = 0; nt < 4; nt++) {
                int cb = (isT ? 132 : 0) + w4*32 + nt*8 + gc*2;
                Csh[(mt*16+gr)*264   + cb]   = cr[nt][0];
                Csh[(mt*16+gr)*264   + cb+1] = cr[nt][1];
                Csh[(mt*16+gr+8)*264 + cb]   = cr[nt][2];
                Csh[(mt*16+gr+8)*264 + cb+1] = cr[nt][3];
            }
        }
        __syncthreads();
        // S: fp32, bias folded in
        #pragma unroll
        for (int i = 0; i < 4; i++) {
            int lin = tid + i*256;
            int r = lin >> 5, c4 = lin & 31;
            float4 v  = *(float4*)&Csh[r*264 + c4*4];
            float4 bi = *(const float4*)&convB[l*C2 + c4*4];
            v.x += bi.x; v.y += bi.y; v.z += bi.z; v.w += bi.w;
            *(float4*)&g_S[(size_t)(a0+r)*C2 + c4*4] = v;
        }
        // T: bf16 (32 rows x 256B)
        #pragma unroll
        for (int i = 0; i < 2; i++) {
            int lin = tid + i*256;
            int r = lin >> 4, c8 = lin & 15;
            const float* src = &Csh[r*264 + 132 + c8*8];
            float4 v0 = *(const float4*)src, v1 = *(const float4*)(src+4);
            __nv_bfloat162 h0 = __float22bfloat162_rn(make_float2(v0.x, v0.y));
            __nv_bfloat162 h1 = __float22bfloat162_rn(make_float2(v0.z, v0.w));
            __nv_bfloat162 h2 = __float22bfloat162_rn(make_float2(v1.x, v1.y));
            __nv_bfloat162 h3 = __float22bfloat162_rn(make_float2(v1.z, v1.w));
            uint4 pk;
            pk.x = *(unsigned*)&h0; pk.y = *(unsigned*)&h1;
            pk.z = *(unsigned*)&h2; pk.w = *(unsigned*)&h3;
            *(uint4*)((char*)g_T + (size_t)(a0+r)*256 + c8*16) = pk;
        }
        __syncthreads();
    }
}

// ======= conv pass machinery (4 warps, 32 ch/warp) ===========================
__device__ __forceinline__ void prefetch_tile(int t, uint32_t bb,
        const float* __restrict__ nbr_fea, const int* __restrict__ idx, int tid) {
    const char* asrc = (const char*)nbr_fea + (size_t)t * A_BYTES;
    #pragma unroll
    for (int i = 0; i < 4; i++) {
        int c = tid + i*128;
        if (c < A_CHUNK) cp16(bb + c*16, asrc + c*16);
    }
    int p0 = t * TILE;
    #pragma unroll
    for (int i = 0; i < 6; i++) {               // bf16 T rows: 256B each
        int lin = tid + i*128;
        int r = lin >> 4, cx = lin & 15;
        int j = __ldg(&idx[p0 + r]);
        cp16(bb + T_OFF + r*TROWB + cx*16, (const char*)g_T + ((size_t)j << 8) + cx*16);
    }
    { int r = tid >> 5, cx = tid & 31;           // fp32 S rows: 512B each
      cp16(bb + S_OFF + r*528 + cx*16,
           (const char*)g_S + ((size_t)(t*4 + r) << 9) + cx*16); }
    cp_commit();
}

#define PASS_PROLOG \
    const float* W3 = convW + (size_t)l*FIN*C2 + (size_t)C2*C2;                 \
    int tid  = threadIdx.x;                                                     \
    int warp = tid >> 5, lane = tid & 31;                                       \
    int gr = lane >> 2, gc = lane & 3;                                          \
    unsigned bfr[5][4][2];                                                      \
    _Pragma("unroll") for (int ks = 0; ks < 5; ks++)                            \
        _Pragma("unroll") for (int nt = 0; nt < 4; nt++) {                      \
            int c  = CHBASE(warp, nt) + gr;                                     \
            int k0 = ks*8 + gc, k1 = k0 + 4;                                    \
            bfr[ks][nt][0] = f2tf32(W3[k0*C2 + c]);                             \
            bfr[ks][nt][1] = f2tf32(W3[k1*C2 + c]);                             \
        }                                                                       \
    float w40[4][2];                                                            \
    _Pragma("unroll") for (int nt = 0; nt < 4; nt++) {                          \
        w40[nt][0] = W3[40*C2 + CHBASE(warp, nt) + gc*2];                       \
        w40[nt][1] = W3[40*C2 + CHBASE(warp, nt) + gc*2 + 1];                   \
    }                                                                           \
    extern __shared__ char smx[];                                               \
    uint32_t sbase = (uint32_t)__cvta_generic_to_shared(smx);

// MMA over k=0..39 (tf32), then k=40 via fp32 FFMA (identical in both passes).
#define DO_MMA(mt, cr, Au, Af) \
        _Pragma("unroll") for (int ks = 0; ks < 5; ks++) {                      \
            unsigned a0 = Au[((mt)*16+gr)*NBRF   + ks*8+gc];                    \
            unsigned a1 = Au[((mt)*16+gr+8)*NBRF + ks*8+gc];                    \
            unsigned a2 = Au[((mt)*16+gr)*NBRF   + ks*8+gc+4];                  \
            unsigned a3 = Au[((mt)*16+gr+8)*NBRF + ks*8+gc+4];                  \
            _Pragma("unroll") for (int nt = 0; nt < 4; nt++)                    \
                MMA_TF32(cr[nt], a0, a1, a2, a3, bfr[ks][nt][0], bfr[ks][nt][1]); \
        }                                                                       \
        {   float a40_0 = Af[((mt)*16+gr)*NBRF + 40];                           \
            float a40_1 = Af[((mt)*16+gr+8)*NBRF + 40];                         \
            _Pragma("unroll") for (int nt = 0; nt < 4; nt++) {                  \
                cr[nt][0] += a40_0*w40[nt][0];  cr[nt][1] += a40_0*w40[nt][1];  \
                cr[nt][2] += a40_1*w40[nt][0];  cr[nt][3] += a40_1*w40[nt][1];  \
            }                                                                   \
        }

// ---------------- pass 1: BN1 statistics + fused reduce ----------------------
__global__ void __launch_bounds__(128, 4) k_stats(const float* __restrict__ nbr_fea,
        const int* __restrict__ idx, const float* __restrict__ convW,
        const float* __restrict__ g1, const float* __restrict__ be1, int l) {
    PASS_PROLOG
    float sch[4][2] = {}, sch2[4][2] = {};
    int t = blockIdx.x;
    prefetch_tile(t, sbase, nbr_fea, idx, tid);
    int cur = 0;
    for (; t < NTILE; t += NB) {
        int tn = t + NB;
        if (tn < NTILE) {
            prefetch_tile(tn, sbase + (1-cur)*BUFSZ, nbr_fea, idx, tid);
            asm volatile("cp.async.wait_group 1;\n");
        } else {
            asm volatile("cp.async.wait_group 0;\n");
        }
        __syncthreads();
        const unsigned* Au = (const unsigned*)(smx + cur*BUFSZ);
        const float*    Af = (const float*)(smx + cur*BUFSZ);
        const char*     TB = smx + cur*BUFSZ + T_OFF;
        const float*    Ssh = (const float*)(smx + cur*BUFSZ + S_OFF);
        #pragma unroll
        for (int mt = 0; mt < 3; mt++) {
            float cr[4][4] = {};
            DO_MMA(mt, cr, Au, Af)
            int r0 = mt*16 + gr, r1 = r0 + 8;
            int a0i = r0 / MNBR, a1i = r1 / MNBR;
            #pragma unroll
            for (int nt = 0; nt < 4; nt++) {
                int c0 = CHBASE(warp, nt) + gc*2;
                float2 t0 = ldbf2(TB + r0*TROWB + c0*2);
                float2 s0 = *(const float2*)&Ssh[a0i*SROW + c0];
                float2 t1 = ldbf2(TB + r1*TROWB + c0*2);
                float2 s1 = *(const float2*)&Ssh[a1i*SROW + c0];
                float v;
                v = cr[nt][0] + t0.x + s0.x; sch[nt][0] += v; sch2[nt][0] += v*v;
                v = cr[nt][1] + t0.y + s0.y; sch[nt][1] += v; sch2[nt][1] += v*v;
                v = cr[nt][2] + t1.x + s1.x; sch[nt][0] += v; sch2[nt][0] += v*v;
                v = cr[nt][3] + t1.y + s1.y; sch[nt][1] += v; sch2[nt][1] += v*v;
            }
        }
        __syncthreads();
        cur ^= 1;
    }
    #pragma unroll
    for (int nt = 0; nt < 4; nt++)
        #pragma unroll
        for (int j = 0; j < 2; j++) {
            sch[nt][j]  = bfly3(sch[nt][j]);
            sch2[nt][j] = bfly3(sch2[nt][j]);
        }
    if (lane < 4) {
        #pragma unroll
        for (int nt = 0; nt < 4; nt++)
            #pragma unroll
            for (int j = 0; j < 2; j++) {
                int c = CHBASE(warp, nt) + lane*2 + j;
                g_part1[blockIdx.x*C2 + c] = sch[nt][j];
                g_part2[blockIdx.x*C2 + c] = sch2[nt][j];
            }
    }
    __shared__ int amLast;
    __threadfence();
    __syncthreads();
    if (tid == 0) amLast = (atomicAdd(&g_c1, 1u) == NB - 1);
    __syncthreads();
    if (amLast) {
        int c = tid;
        float s = 0.f, s2 = 0.f;
        for (int i = 0; i < NB; i++) {
            s += g_part1[i*C2 + c]; s2 += g_part2[i*C2 + c];
        }
        float cnt  = (float)((size_t)NATOMS * MNBR);
        float mean = s / cnt;
        float var  = s2 / cnt - mean*mean;
        float rstd = rsqrtf(var + EPSBN);
        float sc   = g1[l*C2 + c] * rstd;
        g_scale1[c] = sc;
        g_shift1[c] = be1[l*C2 + c] - mean*sc;
        if (tid == 0) g_c1 = 0;
    }
}

// ---------------- pass 2: recompute + activation + shfl nbr-sum + fused BN2 --
__global__ void __launch_bounds__(128, 4) k_conv(const float* __restrict__ nbr_fea,
        const int* __restrict__ idx, const float* __restrict__ convW,
        const float* __restrict__ g2, const float* __restrict__ be2, int l) {
    PASS_PROLOG
    float scF[2][2], shF[2][2], scC[2][2], shC[2][2];
    #pragma unroll
    for (int nt = 0; nt < 2; nt++)
        #pragma unroll
        for (int j = 0; j < 2; j++) {
            int cF0 = CHBASE(warp, nt) + gc*2 + j;
            scF[nt][j] = g_scale1[cF0];      shF[nt][j] = g_shift1[cF0];
            scC[nt][j] = g_scale1[cF0+64];   shC[nt][j] = g_shift1[cF0+64];
        }
    float sAc[2][2] = {}, sAc2[2][2] = {};

    int t = blockIdx.x;
    prefetch_tile(t, sbase, nbr_fea, idx, tid);
    int cur = 0;
    for (; t < NTILE; t += NB) {
        int tn = t + NB;
        if (tn < NTILE) {
            prefetch_tile(tn, sbase + (1-cur)*BUFSZ, nbr_fea, idx, tid);
            asm volatile("cp.async.wait_group 1;\n");
        } else {
            asm volatile("cp.async.wait_group 0;\n");
        }
        __syncthreads();
        const unsigned* Au = (const unsigned*)(smx + cur*BUFSZ);
        const float*    Af = (const float*)(smx + cur*BUFSZ);
        const char*     TB = smx + cur*BUFSZ + T_OFF;
        const float*    Ssh = (const float*)(smx + cur*BUFSZ + S_OFF);
        float P[4][2][2] = {};          // atom x nt x j partials (static indices)
        #pragma unroll
        for (int mt = 0; mt < 3; mt++) {
            float cr[4][4] = {};
            DO_MMA(mt, cr, Au, Af)
            #pragma unroll
            for (int rr = 0; rr < 2; rr++) {
                const int slot = mt*2 + rr;            // rows [slot*8, slot*8+8)
                const int alo = (slot*8) / MNBR;
                const int ahi = (slot*8 + 7) / MNBR;
                int r  = slot*8 + gr;
                int ai = (alo == ahi) ? alo : ((gr < 4) ? alo : ahi);
                #pragma unroll
                for (int nt = 0; nt < 2; nt++) {
                    int cF = CHBASE(warp, nt) + gc*2;
                    int cC = cF + 64;
                    float2 tF = ldbf2(TB + r*TROWB + cF*2);
                    float2 sF = *(const float2*)&Ssh[ai*SROW + cF];
                    float2 tC = ldbf2(TB + r*TROWB + cC*2);
                    float2 sC = *(const float2*)&Ssh[ai*SROW + cC];
                    float F0 = cr[nt][rr*2]     + tF.x + sF.x;
                    float F1 = cr[nt][rr*2+1]   + tF.y + sF.y;
                    float C0 = cr[nt+2][rr*2]   + tC.x + sC.x;
                    float C1 = cr[nt+2][rr*2+1] + tC.y + sC.y;
                    float a0v = sigt(F0*scF[nt][0] + shF[nt][0]) * sp(C0*scC[nt][0] + shC[nt][0]);
                    float a1v = sigt(F1*scF[nt][1] + shF[nt][1]) * sp(C1*scC[nt][1] + shC[nt][1]);
                    if (alo == ahi) {
                        P[alo][nt][0] += a0v; P[alo][nt][1] += a1v;
                    } else if (gr < 4) {
                        P[alo][nt][0] += a0v; P[alo][nt][1] += a1v;
                    } else {
                        P[ahi][nt][0] += a0v; P[ahi][nt][1] += a1v;
                    }
                }
            }
        }
        // butterfly over gr lanes -> every lane holds full 12-neighbor sums
        #pragma unroll
        for (int a = 0; a < 4; a++)
            #pragma unroll
            for (int nt = 0; nt < 2; nt++)
                #pragma unroll
                for (int j = 0; j < 2; j++)
                    P[a][nt][j] = bfly3(P[a][nt][j]);
        // lane gr==a stores atom a; accumulate BN2 partials
        #pragma unroll
        for (int a = 0; a < 4; a++) {
            if (gr == a) {
                #pragma unroll
                for (int nt = 0; nt < 2; nt++) {
                    float2 st = make_float2(P[a][nt][0], P[a][nt][1]);
                    *(float2*)&g_nbrsum[(size_t)(t*4 + a)*AF + CHBASE(warp, nt) + gc*2] = st;
                    #pragma unroll
                    for (int j = 0; j < 2; j++) {
                        sAc[nt][j]  += P[a][nt][j];
                        sAc2[nt][j] += P[a][nt][j]*P[a][nt][j];
                    }
                }
            }
        }
        __syncthreads();
        cur ^= 1;
    }
    #pragma unroll
    for (int nt = 0; nt < 2; nt++)
        #pragma unroll
        for (int j = 0; j < 2; j++) {
            sAc[nt][j]  = bfly3(sAc[nt][j]);
            sAc2[nt][j] = bfly3(sAc2[nt][j]);
        }
    if (lane < 4) {
        #pragma unroll
        for (int nt = 0; nt < 2; nt++)
            #pragma unroll
            for (int j = 0; j < 2; j++) {
                int c = CHBASE(warp, nt) + lane*2 + j;
                g_partA[blockIdx.x*AF + c] = sAc[nt][j];
                g_partB[blockIdx.x*AF + c] = sAc2[nt][j];
            }
    }
    // fused BN2 reduce
    __shared__ int amLast;
    __threadfence();
    __syncthreads();
    if (tid == 0) amLast = (atomicAdd(&g_c2, 1u) == NB - 1);
    __syncthreads();
    if (amLast && tid < AF) {
        int c = tid;
        float s = 0.f, s2 = 0.f;
        for (int i = 0; i < NB; i++) {
            s += g_partA[i*AF + c]; s2 += g_partB[i*AF + c];
        }
        float cnt  = (float)NATOMS;
        float mean = s / cnt;
        float var  = s2 / cnt - mean*mean;
        float rstd = rsqrtf(var + EPSBN);
        float sc   = g2[l*AF + c] * rstd;
        g_scale2[c] = sc;
        g_shift2[c] = be2[l*AF + c] - mean*sc;
        if (tid == 0) g_c2 = 0;
    }
}

// ---------------- finish: final update + segment mean pool + MLP head --------
__global__ void __launch_bounds__(128) k_finish(const int* __restrict__ cidx,
        const float* __restrict__ W1, const float* __restrict__ b1,
        const float* __restrict__ W2, const float* __restrict__ b2,
        float* __restrict__ out, float* __restrict__ out_crys) {
    int b = blockIdx.x, tid = threadIdx.x;
    int lo = lbound(cidx, NATOMS, b);
    int hi = lbound(cidx, NATOMS, b + 1);
    int f = tid & 63, half = tid >> 6;
    float sc2 = g_scale2[f], sh2v = g_shift2[f];
    float s = 0.f;
    for (int a = lo + half; a < hi; a += 2) {
        size_t i = (size_t)a*AF + f;
        s += sp(g_x[i] + g_nbrsum[i]*sc2 + sh2v);
    }
    __shared__ float psum[2][AF];
    __shared__ float av[AF];
    __shared__ float red[HDIM];
    psum[half][f] = s;
    __syncthreads();
    if (tid < AF) {
        float v = (psum[0][tid] + psum[1][tid]) / fmaxf((float)(hi - lo), 1.f);
        out_crys[b*AF + tid] = v;
        av[tid] = sp(v);
    }
    __syncthreads();
    for (int p = 0; p < NPROP; p++) {
        float acc = b1[p*HDIM + tid];
        #pragma unroll
        for (int k = 0; k < AF; k++) acc += av[k] * W1[((size_t)p*AF + k)*HDIM + tid];
        red[tid] = sp(acc) * W2[p*HDIM + tid];
        __syncthreads();
        for (int o = 64; o > 0; o >>= 1) {
            if (tid < o) red[tid] += red[tid+o];
            __syncthreads();
        }
        if (tid == 0) out[b*NPROP + p] = red[0] + b2[p];
        __syncthreads();
    }
}

// ---------------- launch --------------------------------------------------------
extern "C" void kernel_launch(void* const* d_in, const int* in_sizes, int n_in,
                              void* d_out, int out_size) {
    const float* atom_fea = (const float*)d_in[0];
    const float* nbr_fea  = (const float*)d_in[1];
    const float* W_embed  = (const float*)d_in[2];
    const float* b_embed  = (const float*)d_in[3];
    const float* conv_W   = (const float*)d_in[4];
    const float* conv_b   = (const float*)d_in[5];
    const float* conv_g1  = (const float*)d_in[6];
    const float* conv_be1 = (const float*)d_in[7];
    const float* conv_g2  = (const float*)d_in[8];
    const float* conv_be2 = (const float*)d_in[9];
    const float* head_W1  = (const float*)d_in[10];
    const float* head_b1  = (const float*)d_in[11];
    const float* head_W2  = (const float*)d_in[12];
    const float* head_b2  = (const float*)d_in[13];
    const int*   nbr_idx  = (const int*)d_in[14];
    const int*   cidx     = (const int*)d_in[15];
    float* out = (float*)d_out;

    cudaFuncSetAttribute(k_stats, cudaFuncAttributeMaxDynamicSharedMemorySize, DSMEM);
    cudaFuncSetAttribute(k_conv,  cudaFuncAttributeMaxDynamicSharedMemorySize, DSMEM);

    k_embed<<<2048, 128>>>(atom_fea, W_embed, b_embed);
    for (int l = 0; l < NCONV; l++) {
        k_proj  <<<2048, 256>>>(conv_W, conv_b, l, l > 0);
        k_stats <<<NB, 128, DSMEM>>>(nbr_fea, nbr_idx, conv_W,
                                     conv_g1, conv_be1, l);
        k_conv  <<<NB, 128, DSMEM>>>(nbr_fea, nbr_idx, conv_W,
                                     conv_g2, conv_be2, l);
    }
    k_finish<<<NSEG, HDIM>>>(cidx, head_W1, head_b1, head_W2, head_b2,
                             out, out + NSEG*NPROP);
}

// round 17
// speedup vs baseline: 1.2707x; 1.0978x over previous
#include <cuda_runtime.h>
#include <cuda_bf16.h>
#include <cstdint>

#define NATOMS 131072
#define MNBR   12
#define ORIG   92
#define NBRF   41
#define KPAD   48
#define AF     64
#define HDIM   128
#define NPROP  2
#define NCONV  3
#define NSEG   1024
#define FIN    169
#define C2     128
#define EPSBN  1e-5f

#define NPAIR  (NATOMS*MNBR)           // 1572864
#define TILE   48                      // 4 atoms x 12 nbrs
#define NTILE  (NPAIR/TILE)            // 32768
#define NB     592                     // 148 SMs x 4 resident blocks

// conv-pass dynamic smem (double buffered)
#define AROWB   112                    // bf16 row: 96B data padded to 112B (16B mult)
#define A_SM    (TILE*AROWB)           // 5376
#define A_GROW  96                     // global bf16 row bytes (48 x 2)
#define T_OFF   A_SM
#define TROWB   272
#define T_BYTES (TILE*TROWB)           // 13056
#define S_OFF   (T_OFF + T_BYTES)      // fp32 rows padded: 528B (bias folded)
#define SROW    132
#define S_BYTES (4*SROW*4)             // 2112
#define BUFSZ   (S_OFF + S_BYTES)      // 20544
#define DSMEM   (2*BUFSZ)              // 41088

#define CHBASE(w, nt) ((w)*16 + ((nt)&1)*8 + ((nt)>>1)*64)

// ---------------- scratch ----------------------------------------------------
__device__ float g_x[(size_t)NATOMS*AF];
__device__ float g_S[(size_t)NATOMS*C2];
__device__ __nv_bfloat16 g_T[(size_t)NATOMS*C2];
__device__ __nv_bfloat16 g_A[(size_t)NPAIR*KPAD];   // 151 MB, padded bf16 nbr_fea
__device__ float g_nbrsum[(size_t)NATOMS*AF];
__device__ float g_part1[1024*C2];
__device__ float g_part2[1024*C2];
__device__ float g_partA[1024*AF];
__device__ float g_partB[1024*AF];
__device__ float g_scale1[C2], g_shift1[C2];
__device__ float g_scale2[AF], g_shift2[AF];
__device__ unsigned g_c1 = 0, g_c2 = 0;

// ---------------- helpers ----------------------------------------------------
__device__ __forceinline__ float sp(float x) {
    return fmaxf(x, 0.f) + __logf(1.f + __expf(-fabsf(x)));
}
__device__ __forceinline__ float sigt(float x) {
    float t;
    asm("tanh.approx.f32 %0, %1;" : "=f"(t) : "f"(x*0.5f));
    return fmaf(0.5f, t, 0.5f);
}
__device__ __forceinline__ int lbound(const int* __restrict__ a, int n, int v) {
    int lo = 0, hi = n;
    while (lo < hi) { int mid = (lo + hi) >> 1; if (a[mid] < v) lo = mid + 1; else hi = mid; }
    return lo;
}
__device__ __forceinline__ unsigned f2tf32(float v) {
    unsigned u; asm("cvt.rna.tf32.f32 %0, %1;" : "=r"(u) : "f"(v)); return u;
}
__device__ __forceinline__ unsigned packbf2(float a, float b) {
    __nv_bfloat162 h = __float22bfloat162_rn(make_float2(a, b));
    return *(unsigned*)&h;
}
__device__ __forceinline__ void cp16(uint32_t dst, const void* src) {
    asm volatile("cp.async.cg.shared.global [%0], [%1], 16;\n" :: "r"(dst), "l"(src));
}
__device__ __forceinline__ void cp_commit() {
    asm volatile("cp.async.commit_group;\n");
}
__device__ __forceinline__ float bfly3(float v) {
    v += __shfl_xor_sync(0xffffffffu, v, 4);
    v += __shfl_xor_sync(0xffffffffu, v, 8);
    v += __shfl_xor_sync(0xffffffffu, v, 16);
    return v;
}
__device__ __forceinline__ float2 ldbf2(const char* p) {
    __nv_bfloat162 h = *(const __nv_bfloat162*)p;
    return __bfloat1622float2(h);
}

#define MMA_TF32(cr, a0, a1, a2, a3, b0, b1) \
    asm("mma.sync.aligned.m16n8k8.row.col.f32.tf32.tf32.f32 " \
        "{%0,%1,%2,%3}, {%4,%5,%6,%7}, {%8,%9}, {%0,%1,%2,%3};" \
        : "+f"(cr[0]), "+f"(cr[1]), "+f"(cr[2]), "+f"(cr[3]) \
        : "r"(a0), "r"(a1), "r"(a2), "r"(a3), "r"(b0), "r"(b1));

#define MMA_BF16(cr, a0, a1, a2, a3, b0, b1) \
    asm("mma.sync.aligned.m16n8k16.row.col.f32.bf16.bf16.f32 " \
        "{%0,%1,%2,%3}, {%4,%5,%6,%7}, {%8,%9}, {%0,%1,%2,%3};" \
        : "+f"(cr[0]), "+f"(cr[1]), "+f"(cr[2]), "+f"(cr[3]) \
        : "r"(a0), "r"(a1), "r"(a2), "r"(a3), "r"(b0), "r"(b1));

// ---------------- prep: nbr_fea -> padded bf16 (once) ------------------------
__global__ void k_prep(const float* __restrict__ nbr) {
    size_t i = (size_t)blockIdx.x*256 + threadIdx.x;   // over NPAIR*24 uint slots
    size_t p = i / 24;
    int q = (int)(i - p*24);
    int k0 = 2*q, k1 = 2*q + 1;
    float v0 = (k0 < NBRF) ? nbr[p*NBRF + k0] : 0.f;
    float v1 = (k1 < NBRF) ? nbr[p*NBRF + k1] : 0.f;
    ((unsigned*)g_A)[p*24 + q] = packbf2(v0, v1);
}

// ---------------- embed: x = atom_fea @ W_embed + b (tf32 MMA) ---------------
__global__ void __launch_bounds__(128) k_embed(const float* __restrict__ af,
        const float* __restrict__ W, const float* __restrict__ b) {
    int tid = threadIdx.x, warp = tid >> 5, lane = tid & 31;
    int gr = lane >> 2, gc = lane & 3;
    unsigned bfr[12][2][2];
    #pragma unroll
    for (int ks = 0; ks < 12; ks++)
        #pragma unroll
        for (int nt = 0; nt < 2; nt++) {
            int c = warp*16 + nt*8 + gr;
            int k0 = ks*8 + gc, k1 = k0 + 4;
            bfr[ks][nt][0] = f2tf32((k0 < ORIG) ? W[k0*AF + c] : 0.f);
            bfr[ks][nt][1] = f2tf32((k1 < ORIG) ? W[k1*AF + c] : 0.f);
        }
    __shared__ unsigned Ash[32*100];
    __shared__ float Csh[32*68];
    for (int tt = 0; tt < 2; tt++) {
        int t = blockIdx.x + tt*2048;
        int a0 = t*32;
        for (int i = tid; i < 32*100; i += 128) {
            int r = i/100, k = i - r*100;
            float v = (k < ORIG) ? af[(size_t)(a0+r)*ORIG + k] : 0.f;
            Ash[i] = f2tf32(v);
        }
        __syncthreads();
        #pragma unroll
        for (int mt = 0; mt < 2; mt++) {
            float cr[2][4] = {};
            #pragma unroll
            for (int ks = 0; ks < 12; ks++) {
                unsigned a0f = Ash[(mt*16+gr)*100   + ks*8+gc];
                unsigned a1f = Ash[(mt*16+gr+8)*100 + ks*8+gc];
                unsigned a2f = Ash[(mt*16+gr)*100   + ks*8+gc+4];
                unsigned a3f = Ash[(mt*16+gr+8)*100 + ks*8+gc+4];
                #pragma unroll
                for (int nt = 0; nt < 2; nt++)
                    MMA_TF32(cr[nt], a0f, a1f, a2f, a3f, bfr[ks][nt][0], bfr[ks][nt][1]);
            }
            #pragma unroll
            for (int nt = 0; nt < 2; nt++) {
                int cb = warp*16 + nt*8 + gc*2;
                Csh[(mt*16+gr)*68   + cb]   = cr[nt][0];
                Csh[(mt*16+gr)*68   + cb+1] = cr[nt][1];
                Csh[(mt*16+gr+8)*68 + cb]   = cr[nt][2];
                Csh[(mt*16+gr+8)*68 + cb+1] = cr[nt][3];
            }
        }
        __syncthreads();
        #pragma unroll
        for (int i = 0; i < 4; i++) {
            int lin = tid + i*128;
            int r = lin >> 4, c4 = lin & 15;
            float4 v = *(float4*)&Csh[r*68 + c4*4];
            float4 bi = *(const float4*)&b[c4*4];
            v.x += bi.x; v.y += bi.y; v.z += bi.z; v.w += bi.w;
            *(float4*)&g_x[(size_t)(a0+r)*AF + c4*4] = v;
        }
        __syncthreads();
    }
}

// ---------------- proj: [S|T] = x @ W[0:128,:]; bias folded into S (fp32) ----
__global__ void __launch_bounds__(256) k_proj(const float* __restrict__ convW,
        const float* __restrict__ convB, int l, int fuse) {
    const float* W = convW + (size_t)l*FIN*C2;
    int tid = threadIdx.x, warp = tid >> 5, lane = tid & 31;
    int gr = lane >> 2, gc = lane & 3;
    int isT = (warp >= 4), w4 = warp & 3;
    int rbase = isT ? AF : 0;
    unsigned bfr[8][4][2];
    #pragma unroll
    for (int ks = 0; ks < 8; ks++)
        #pragma unroll
        for (int nt = 0; nt < 4; nt++) {
            int c = w4*32 + nt*8 + gr;
            int k0 = ks*8 + gc, k1 = k0 + 4;
            bfr[ks][nt][0] = f2tf32(W[(rbase+k0)*C2 + c]);
            bfr[ks][nt][1] = f2tf32(W[(rbase+k1)*C2 + c]);
        }
    __shared__ unsigned Ash[32*68];
    __shared__ float Csh[32*264];
    for (int tt = 0; tt < 2; tt++) {
        int t = blockIdx.x + tt*2048;
        int a0 = t*32;
        {
            int r = tid >> 3, q = tid & 7;
            size_t base = (size_t)(a0+r)*AF + q*8;
            float4 v0 = *(const float4*)&g_x[base];
            float4 v1 = *(const float4*)&g_x[base+4];
            if (fuse) {
                float4 n0 = *(const float4*)&g_nbrsum[base];
                float4 n1 = *(const float4*)&g_nbrsum[base+4];
                float4 sc0 = *(const float4*)&g_scale2[q*8];
                float4 sc1 = *(const float4*)&g_scale2[q*8+4];
                float4 sh0 = *(const float4*)&g_shift2[q*8];
                float4 sh1 = *(const float4*)&g_shift2[q*8+4];
                v0.x = sp(v0.x + n0.x*sc0.x + sh0.x);
                v0.y = sp(v0.y + n0.y*sc0.y + sh0.y);
                v0.z = sp(v0.z + n0.z*sc0.z + sh0.z);
                v0.w = sp(v0.w + n0.w*sc0.w + sh0.w);
                v1.x = sp(v1.x + n1.x*sc1.x + sh1.x);
                v1.y = sp(v1.y + n1.y*sc1.y + sh1.y);
                v1.z = sp(v1.z + n1.z*sc1.z + sh1.z);
                v1.w = sp(v1.w + n1.w*sc1.w + sh1.w);
                *(float4*)&g_x[base]   = v0;
                *(float4*)&g_x[base+4] = v1;
            }
            unsigned* dst = &Ash[r*68 + q*8];
            dst[0]=f2tf32(v0.x); dst[1]=f2tf32(v0.y); dst[2]=f2tf32(v0.z); dst[3]=f2tf32(v0.w);
            dst[4]=f2tf32(v1.x); dst[5]=f2tf32(v1.y); dst[6]=f2tf32(v1.z); dst[7]=f2tf32(v1.w);
        }
        __syncthreads();
        #pragma unroll
        for (int mt = 0; mt < 2; mt++) {
            float cr[4][4] = {};
            #pragma unroll
            for (int ks = 0; ks < 8; ks++) {
                unsigned a0f = Ash[(mt*16+gr)*68   + ks*8+gc];
                unsigned a1f = Ash[(mt*16+gr+8)*68 + ks*8+gc];
                unsigned a2f = Ash[(mt*16+gr)*68   + ks*8+gc+4];
                unsigned a3f = Ash[(mt*16+gr+8)*68 + ks*8+gc+4];
                #pragma unroll
                for (int nt = 0; nt < 4; nt++)
                    MMA_TF32(cr[nt], a0f, a1f, a2f, a3f, bfr[ks][nt][0], bfr[ks][nt][1]);
            }
            #pragma unroll
            for (int nt = 0; nt < 4; nt++) {
                int cb = (isT ? 132 : 0) + w4*32 + nt*8 + gc*2;
                Csh[(mt*16+gr)*264   + cb]   = cr[nt][0];
                Csh[(mt*16+gr)*264   + cb+1] = cr[nt][1];
                Csh[(mt*16+gr+8)*264 + cb]   = cr[nt][2];
                Csh[(mt*16+gr+8)*264 + cb+1] = cr[nt][3];
            }
        }
        __syncthreads();
        // S: fp32, bias folded in
        #pragma unroll
        for (int i = 0; i < 4; i++) {
            int lin = tid + i*256;
            int r = lin >> 5, c4 = lin & 31;
            float4 v  = *(float4*)&Csh[r*264 + c4*4];
            float4 bi = *(const float4*)&convB[l*C2 + c4*4];
            v.x += bi.x; v.y += bi.y; v.z += bi.z; v.w += bi.w;
            *(float4*)&g_S[(size_t)(a0+r)*C2 + c4*4] = v;
        }
        // T: bf16 (32 rows x 256B)
        #pragma unroll
        for (int i = 0; i < 2; i++) {
            int lin = tid + i*256;
            int r = lin >> 4, c8 = lin & 15;
            const float* src = &Csh[r*264 + 132 + c8*8];
            float4 v0 = *(const float4*)src, v1 = *(const float4*)(src+4);
            uint4 pk;
            pk.x = packbf2(v0.x, v0.y); pk.y = packbf2(v0.z, v0.w);
            pk.z = packbf2(v1.x, v1.y); pk.w = packbf2(v1.z, v1.w);
            *(uint4*)((char*)g_T + (size_t)(a0+r)*256 + c8*16) = pk;
        }
        __syncthreads();
    }
}

// ======= conv pass machinery (4 warps, 32 ch/warp, bf16 MMA) =================
__device__ __forceinline__ void prefetch_tile(int t, uint32_t bb,
        const int* __restrict__ idx, int tid) {
    // A: 48 rows x 96B bf16 (smem stride 112, 16B-aligned)
    #pragma unroll
    for (int i = 0; i < 3; i++) {
        int lin = tid + i*128;
        if (lin < TILE*6) {
            int r = lin / 6, cx = lin - r*6;
            cp16(bb + r*AROWB + cx*16,
                 (const char*)g_A + (size_t)(t*TILE + r)*A_GROW + cx*16);
        }
    }
    int p0 = t * TILE;
    #pragma unroll
    for (int i = 0; i < 6; i++) {               // bf16 T rows: 256B each
        int lin = tid + i*128;
        int r = lin >> 4, cx = lin & 15;
        int j = __ldg(&idx[p0 + r]);
        cp16(bb + T_OFF + r*TROWB + cx*16, (const char*)g_T + ((size_t)j << 8) + cx*16);
    }
    { int r = tid >> 5, cx = tid & 31;           // fp32 S rows: 512B each
      cp16(bb + S_OFF + r*528 + cx*16,
           (const char*)g_S + ((size_t)(t*4 + r) << 9) + cx*16); }
    cp_commit();
}

#define PASS_PROLOG \
    const float* W3 = convW + (size_t)l*FIN*C2 + (size_t)C2*C2;                 \
    int tid  = threadIdx.x;                                                     \
    int warp = tid >> 5, lane = tid & 31;                                       \
    int gr = lane >> 2, gc = lane & 3;                                          \
    unsigned bfr[3][4][2];                                                      \
    _Pragma("unroll") for (int ks = 0; ks < 3; ks++)                            \
        _Pragma("unroll") for (int nt = 0; nt < 4; nt++) {                      \
            int c  = CHBASE(warp, nt) + gr;                                     \
            int ka = ks*16 + 2*gc, kb = ka + 8;                                 \
            float wa0 = (ka   < NBRF) ? W3[ka*C2 + c]     : 0.f;                \
            float wa1 = (ka+1 < NBRF) ? W3[(ka+1)*C2 + c] : 0.f;                \
            float wb0 = (kb   < NBRF) ? W3[kb*C2 + c]     : 0.f;                \
            float wb1 = (kb+1 < NBRF) ? W3[(kb+1)*C2 + c] : 0.f;                \
            bfr[ks][nt][0] = packbf2(wa0, wa1);                                 \
            bfr[ks][nt][1] = packbf2(wb0, wb1);                                 \
        }                                                                       \
    extern __shared__ char smx[];                                               \
    uint32_t sbase = (uint32_t)__cvta_generic_to_shared(smx);

// bf16 MMA over K=48 (3 ksteps of k16); identical in both passes.
#define DO_MMA(mt, cr, AB) \
        _Pragma("unroll") for (int ks = 0; ks < 3; ks++) {                      \
            unsigned a0 = *(const unsigned*)(AB + ((mt)*16+gr)*AROWB   + ks*32 + gc*4);      \
            unsigned a1 = *(const unsigned*)(AB + ((mt)*16+gr+8)*AROWB + ks*32 + gc*4);      \
            unsigned a2 = *(const unsigned*)(AB + ((mt)*16+gr)*AROWB   + ks*32 + gc*4 + 16); \
            unsigned a3 = *(const unsigned*)(AB + ((mt)*16+gr+8)*AROWB + ks*32 + gc*4 + 16); \
            _Pragma("unroll") for (int nt = 0; nt < 4; nt++)                    \
                MMA_BF16(cr[nt], a0, a1, a2, a3, bfr[ks][nt][0], bfr[ks][nt][1]); \
        }

// ---------------- pass 1: BN1 statistics + fused reduce ----------------------
__global__ void __launch_bounds__(128, 4) k_stats(const int* __restrict__ idx,
        const float* __restrict__ convW,
        const float* __restrict__ g1, const float* __restrict__ be1, int l) {
    PASS_PROLOG
    float sch[4][2] = {}, sch2[4][2] = {};
    int t = blockIdx.x;
    prefetch_tile(t, sbase, idx, tid);
    int cur = 0;
    for (; t < NTILE; t += NB) {
        int tn = t + NB;
        if (tn < NTILE) {
            prefetch_tile(tn, sbase + (1-cur)*BUFSZ, idx, tid);
            asm volatile("cp.async.wait_group 1;\n");
        } else {
            asm volatile("cp.async.wait_group 0;\n");
        }
        __syncthreads();
        const char*  AB = smx + cur*BUFSZ;
        const char*  TB = smx + cur*BUFSZ + T_OFF;
        const float* Ssh = (const float*)(smx + cur*BUFSZ + S_OFF);
        #pragma unroll
        for (int mt = 0; mt < 3; mt++) {
            float cr[4][4] = {};
            DO_MMA(mt, cr, AB)
            int r0 = mt*16 + gr, r1 = r0 + 8;
            int a0i = r0 / MNBR, a1i = r1 / MNBR;
            #pragma unroll
            for (int nt = 0; nt < 4; nt++) {
                int c0 = CHBASE(warp, nt) + gc*2;
                float2 t0 = ldbf2(TB + r0*TROWB + c0*2);
                float2 s0 = *(const float2*)&Ssh[a0i*SROW + c0];
                float2 t1 = ldbf2(TB + r1*TROWB + c0*2);
                float2 s1 = *(const float2*)&Ssh[a1i*SROW + c0];
                float v;
                v = cr[nt][0] + t0.x + s0.x; sch[nt][0] += v; sch2[nt][0] += v*v;
                v = cr[nt][1] + t0.y + s0.y; sch[nt][1] += v; sch2[nt][1] += v*v;
                v = cr[nt][2] + t1.x + s1.x; sch[nt][0] += v; sch2[nt][0] += v*v;
                v = cr[nt][3] + t1.y + s1.y; sch[nt][1] += v; sch2[nt][1] += v*v;
            }
        }
        __syncthreads();
        cur ^= 1;
    }
    #pragma unroll
    for (int nt = 0; nt < 4; nt++)
        #pragma unroll
        for (int j = 0; j < 2; j++) {
            sch[nt][j]  = bfly3(sch[nt][j]);
            sch2[nt][j] = bfly3(sch2[nt][j]);
        }
    if (lane < 4) {
        #pragma unroll
        for (int nt = 0; nt < 4; nt++)
            #pragma unroll
            for (int j = 0; j < 2; j++) {
                int c = CHBASE(warp, nt) + lane*2 + j;
                g_part1[blockIdx.x*C2 + c] = sch[nt][j];
                g_part2[blockIdx.x*C2 + c] = sch2[nt][j];
            }
    }
    __shared__ int amLast;
    __threadfence();
    __syncthreads();
    if (tid == 0) amLast = (atomicAdd(&g_c1, 1u) == NB - 1);
    __syncthreads();
    if (amLast) {
        int c = tid;
        float s = 0.f, s2 = 0.f;
        for (int i = 0; i < NB; i++) {
            s += g_part1[i*C2 + c]; s2 += g_part2[i*C2 + c];
        }
        float cnt  = (float)((size_t)NATOMS * MNBR);
        float mean = s / cnt;
        float var  = s2 / cnt - mean*mean;
        float rstd = rsqrtf(var + EPSBN);
        float sc   = g1[l*C2 + c] * rstd;
        g_scale1[c] = sc;
        g_shift1[c] = be1[l*C2 + c] - mean*sc;
        if (tid == 0) g_c1 = 0;
    }
}

// ---------------- pass 2: recompute + activation + shfl nbr-sum + fused BN2 --
__global__ void __launch_bounds__(128, 4) k_conv(const int* __restrict__ idx,
        const float* __restrict__ convW,
        const float* __restrict__ g2, const float* __restrict__ be2, int l) {
    PASS_PROLOG
    float scF[2][2], shF[2][2], scC[2][2], shC[2][2];
    #pragma unroll
    for (int nt = 0; nt < 2; nt++)
        #pragma unroll
        for (int j = 0; j < 2; j++) {
            int cF0 = CHBASE(warp, nt) + gc*2 + j;
            scF[nt][j] = g_scale1[cF0];      shF[nt][j] = g_shift1[cF0];
            scC[nt][j] = g_scale1[cF0+64];   shC[nt][j] = g_shift1[cF0+64];
        }
    float sAc[2][2] = {}, sAc2[2][2] = {};

    int t = blockIdx.x;
    prefetch_tile(t, sbase, idx, tid);
    int cur = 0;
    for (; t < NTILE; t += NB) {
        int tn = t + NB;
        if (tn < NTILE) {
            prefetch_tile(tn, sbase + (1-cur)*BUFSZ, idx, tid);
            asm volatile("cp.async.wait_group 1;\n");
        } else {
            asm volatile("cp.async.wait_group 0;\n");
        }
        __syncthreads();
        const char*  AB = smx + cur*BUFSZ;
        const char*  TB = smx + cur*BUFSZ + T_OFF;
        const float* Ssh = (const float*)(smx + cur*BUFSZ + S_OFF);
        float P[4][2][2] = {};
        #pragma unroll
        for (int mt = 0; mt < 3; mt++) {
            float cr[4][4] = {};
            DO_MMA(mt, cr, AB)
            #pragma unroll
            for (int rr = 0; rr < 2; rr++) {
                const int slot = mt*2 + rr;
                const int alo = (slot*8) / MNBR;
                const int ahi = (slot*8 + 7) / MNBR;
                int r  = slot*8 + gr;
                int ai = (alo == ahi) ? alo : ((gr < 4) ? alo : ahi);
                #pragma unroll
                for (int nt = 0; nt < 2; nt++) {
                    int cF = CHBASE(warp, nt) + gc*2;
                    int cC = cF + 64;
                    float2 tF = ldbf2(TB + r*TROWB + cF*2);
                    float2 sF = *(const float2*)&Ssh[ai*SROW + cF];
                    float2 tC = ldbf2(TB + r*TROWB + cC*2);
                    float2 sC = *(const float2*)&Ssh[ai*SROW + cC];
                    float F0 = cr[nt][rr*2]     + tF.x + sF.x;
                    float F1 = cr[nt][rr*2+1]   + tF.y + sF.y;
                    float C0 = cr[nt+2][rr*2]   + tC.x + sC.x;
                    float C1 = cr[nt+2][rr*2+1] + tC.y + sC.y;
                    float a0v = sigt(F0*scF[nt][0] + shF[nt][0]) * sp(C0*scC[nt][0] + shC[nt][0]);
                    float a1v = sigt(F1*scF[nt][1] + shF[nt][1]) * sp(C1*scC[nt][1] + shC[nt][1]);
                    if (alo == ahi) {
                        P[alo][nt][0] += a0v; P[alo][nt][1] += a1v;
                    } else if (gr < 4) {
                        P[alo][nt][0] += a0v; P[alo][nt][1] += a1v;
                    } else {
                        P[ahi][nt][0] += a0v; P[ahi][nt][1] += a1v;
                    }
                }
            }
        }
        #pragma unroll
        for (int a = 0; a < 4; a++)
            #pragma unroll
            for (int nt = 0; nt < 2; nt++)
                #pragma unroll
                for (int j = 0; j < 2; j++)
                    P[a][nt][j] = bfly3(P[a][nt][j]);
        #pragma unroll
        for (int a = 0; a < 4; a++) {
            if (gr == a) {
                #pragma unroll
                for (int nt = 0; nt < 2; nt++) {
                    float2 st = make_float2(P[a][nt][0], P[a][nt][1]);
                    *(float2*)&g_nbrsum[(size_t)(t*4 + a)*AF + CHBASE(warp, nt) + gc*2] = st;
                    #pragma unroll
                    for (int j = 0; j < 2; j++) {
                        sAc[nt][j]  += P[a][nt][j];
                        sAc2[nt][j] += P[a][nt][j]*P[a][nt][j];
                    }
                }
            }
        }
        __syncthreads();
        cur ^= 1;
    }
    #pragma unroll
    for (int nt = 0; nt < 2; nt++)
        #pragma unroll
        for (int j = 0; j < 2; j++) {
            sAc[nt][j]  = bfly3(sAc[nt][j]);
            sAc2[nt][j] = bfly3(sAc2[nt][j]);
        }
    if (lane < 4) {
        #pragma unroll
        for (int nt = 0; nt < 2; nt++)
            #pragma unroll
            for (int j = 0; j < 2; j++) {
                int c = CHBASE(warp, nt) + lane*2 + j;
                g_partA[blockIdx.x*AF + c] = sAc[nt][j];
                g_partB[blockIdx.x*AF + c] = sAc2[nt][j];
            }
    }
    __shared__ int amLast;
    __threadfence();
    __syncthreads();
    if (tid == 0) amLast = (atomicAdd(&g_c2, 1u) == NB - 1);
    __syncthreads();
    if (amLast && tid < AF) {
        int c = tid;
        float s = 0.f, s2 = 0.f;
        for (int i = 0; i < NB; i++) {
            s += g_partA[i*AF + c]; s2 += g_partB[i*AF + c];
        }
        float cnt  = (float)NATOMS;
        float mean = s / cnt;
        float var  = s2 / cnt - mean*mean;
        float rstd = rsqrtf(var + EPSBN);
        float sc   = g2[l*AF + c] * rstd;
        g_scale2[c] = sc;
        g_shift2[c] = be2[l*AF + c] - mean*sc;
        if (tid == 0) g_c2 = 0;
    }
}

// ---------------- finish: final update + segment mean pool + MLP head --------
__global__ void __launch_bounds__(128) k_finish(const int* __restrict__ cidx,
        const float* __restrict__ W1, const float* __restrict__ b1,
        const float* __restrict__ W2, const float* __restrict__ b2,
        float* __restrict__ out, float* __restrict__ out_crys) {
    int b = blockIdx.x, tid = threadIdx.x;
    int lo = lbound(cidx, NATOMS, b);
    int hi = lbound(cidx, NATOMS, b + 1);
    int f = tid & 63, half = tid >> 6;
    float sc2 = g_scale2[f], sh2v = g_shift2[f];
    float s = 0.f;
    for (int a = lo + half; a < hi; a += 2) {
        size_t i = (size_t)a*AF + f;
        s += sp(g_x[i] + g_nbrsum[i]*sc2 + sh2v);
    }
    __shared__ float psum[2][AF];
    __shared__ float av[AF];
    __shared__ float red[HDIM];
    psum[half][f] = s;
    __syncthreads();
    if (tid < AF) {
        float v = (psum[0][tid] + psum[1][tid]) / fmaxf((float)(hi - lo), 1.f);
        out_crys[b*AF + tid] = v;
        av[tid] = sp(v);
    }
    __syncthreads();
    for (int p = 0; p < NPROP; p++) {
        float acc = b1[p*HDIM + tid];
        #pragma unroll
        for (int k = 0; k < AF; k++) acc += av[k] * W1[((size_t)p*AF + k)*HDIM + tid];
        red[tid] = sp(acc) * W2[p*HDIM + tid];
        __syncthreads();
        for (int o = 64; o > 0; o >>= 1) {
            if (tid < o) red[tid] += red[tid+o];
            __syncthreads();
        }
        if (tid == 0) out[b*NPROP + p] = red[0] + b2[p];
        __syncthreads();
    }
}

// ---------------- launch --------------------------------------------------------
extern "C" void kernel_launch(void* const* d_in, const int* in_sizes, int n_in,
                              void* d_out, int out_size) {
    const float* atom_fea = (const float*)d_in[0];
    const float* nbr_fea  = (const float*)d_in[1];
    const float* W_embed  = (const float*)d_in[2];
    const float* b_embed  = (const float*)d_in[3];
    const float* conv_W   = (const float*)d_in[4];
    const float* conv_b   = (const float*)d_in[5];
    const float* conv_g1  = (const float*)d_in[6];
    const float* conv_be1 = (const float*)d_in[7];
    const float* conv_g2  = (const float*)d_in[8];
    const float* conv_be2 = (const float*)d_in[9];
    const float* head_W1  = (const float*)d_in[10];
    const float* head_b1  = (const float*)d_in[11];
    const float* head_W2  = (const float*)d_in[12];
    const float* head_b2  = (const float*)d_in[13];
    const int*   nbr_idx  = (const int*)d_in[14];
    const int*   cidx     = (const int*)d_in[15];
    float* out = (float*)d_out;

    cudaFuncSetAttribute(k_stats, cudaFuncAttributeMaxDynamicSharedMemorySize, DSMEM);
    cudaFuncSetAttribute(k_conv,  cudaFuncAttributeMaxDynamicSharedMemorySize, DSMEM);

    k_prep <<<(NPAIR*24)/256, 256>>>(nbr_fea);
    k_embed<<<2048, 128>>>(atom_fea, W_embed, b_embed);
    for (int l = 0; l < NCONV; l++) {
        k_proj  <<<2048, 256>>>(conv_W, conv_b, l, l > 0);
        k_stats <<<NB, 128, DSMEM>>>(nbr_idx, conv_W, conv_g1, conv_be1, l);
        k_conv  <<<NB, 128, DSMEM>>>(nbr_idx, conv_W, conv_g2, conv_be2, l);
    }
    k_finish<<<NSEG, HDIM>>>(cidx, head_W1, head_b1, head_W2, head_b2,
                             out, out + NSEG*NPROP);
}